// round 1
// baseline (speedup 1.0000x reference)
#include <cuda_runtime.h>

// ---------------------------------------------------------------------------
// Net_9560597201379 : SNN encoder/decoder, restructured.
//
// x[8,128,512] -> cur1=x@W1^T+b1 [1024,256]
// s1[k] = elementwise fn of cur1 (m1 indep of m2)   -> s1 [8,1024,256] in {0,1}
// cur2 = s1@W2^T+b2 [8192,128]
// m2 scan over k (elementwise)                      -> spk [8,1024,128]
// cur3 = spk@W3^T+b3 [8192,256]
// s3[j] = elementwise fn of cur3                    -> s3 [8,8192,256]
// cur4 = s3@W4^T+b4 [65536,512]   (the big GEMM, 17.2 GFLOP)
// m4 scan over j -> mem_rec_1 [8,8,8,128,512], spk_rec_1 = (m4>20000)
// Output: mem_rec_1 then spk_rec_1 (tuple order), 2*33554432 floats.
// ---------------------------------------------------------------------------

__device__ float g_cur1[1024*256];
__device__ float g_s1  [8*1024*256];
__device__ float g_cur2[8*1024*128];
__device__ float g_spk [8*1024*128];
__device__ float g_cur3[8*1024*256];
__device__ float g_s3  [8*8192*256];
__device__ float g_cur4[8*8192*512];

#define BM 128
#define BN 128
#define BK 8
#define TM 8
#define TN 8

__device__ __forceinline__ void ffma2(unsigned long long& d,
                                      unsigned long long a,
                                      unsigned long long b) {
    asm("fma.rn.f32x2 %0, %1, %2, %0;" : "+l"(d) : "l"(a), "l"(b));
}

// C[M,N] = A[M,K] * B[N,K]^T + bias[N].  M%128==0, N%128==0, K%8==0.
// Inner loop uses packed f32x2 FMA: acc pairs over M, B value duplicated in smem.
__global__ __launch_bounds__(256, 2) void sgemm_bt(
    const float* __restrict__ A, const float* __restrict__ B,
    const float* __restrict__ bias, float* __restrict__ C,
    int M, int N, int K)
{
    __shared__ float  As[BK][BM];   // A tile transposed: As[k][m]
    __shared__ float2 Bs[BK][BN];   // B tile transposed + duplicated: {b,b}

    const int tid = threadIdx.x;
    const int bx = blockIdx.x, by = blockIdx.y;

    const int lRow = tid >> 1;           // 0..127
    const int lCol = (tid & 1) * 4;      // 0 or 4 (within BK)

    const float* Ab = A + (size_t)by * BM * K;
    const float* Bb = B + (size_t)bx * BN * K;

    const int tr = (tid >> 4) * TM;      // row offset of thread tile
    const int tc = (tid & 15) * TN;      // col offset of thread tile

    unsigned long long acc[TM/2][TN];
#pragma unroll
    for (int i = 0; i < TM/2; i++)
#pragma unroll
        for (int j = 0; j < TN; j++) acc[i][j] = 0ull;

    for (int k0 = 0; k0 < K; k0 += BK) {
        float4 a4 = *reinterpret_cast<const float4*>(Ab + (size_t)lRow * K + k0 + lCol);
        As[lCol+0][lRow] = a4.x;
        As[lCol+1][lRow] = a4.y;
        As[lCol+2][lRow] = a4.z;
        As[lCol+3][lRow] = a4.w;
        float4 b4 = *reinterpret_cast<const float4*>(Bb + (size_t)lRow * K + k0 + lCol);
        Bs[lCol+0][lRow] = make_float2(b4.x, b4.x);
        Bs[lCol+1][lRow] = make_float2(b4.y, b4.y);
        Bs[lCol+2][lRow] = make_float2(b4.z, b4.z);
        Bs[lCol+3][lRow] = make_float2(b4.w, b4.w);
        __syncthreads();
#pragma unroll
        for (int kk = 0; kk < BK; kk++) {
            unsigned long long a2[TM/2], b2[TN];
#pragma unroll
            for (int i = 0; i < TM/2; i++)
                a2[i] = *reinterpret_cast<const unsigned long long*>(&As[kk][tr + 2*i]);
#pragma unroll
            for (int j = 0; j < TN; j++)
                b2[j] = *reinterpret_cast<const unsigned long long*>(&Bs[kk][tc + j]);
#pragma unroll
            for (int i = 0; i < TM/2; i++)
#pragma unroll
                for (int j = 0; j < TN; j++)
                    ffma2(acc[i][j], a2[i], b2[j]);
        }
        __syncthreads();
    }

    float bsv[TN];
#pragma unroll
    for (int j = 0; j < TN; j++) bsv[j] = bias[bx*BN + tc + j];

#pragma unroll
    for (int i = 0; i < TM/2; i++) {
#pragma unroll
        for (int h = 0; h < 2; h++) {
            int m = by*BM + tr + 2*i + h;
            float v[TN];
#pragma unroll
            for (int j = 0; j < TN; j++) {
                unsigned int u = h ? (unsigned int)(acc[i][j] >> 32)
                                   : (unsigned int)(acc[i][j] & 0xffffffffull);
                v[j] = __uint_as_float(u) + bsv[j];
            }
            float* Crow = C + (size_t)m * N + bx*BN + tc;
            *reinterpret_cast<float4*>(Crow)     = make_float4(v[0],v[1],v[2],v[3]);
            *reinterpret_cast<float4*>(Crow + 4) = make_float4(v[4],v[5],v[6],v[7]);
        }
    }
}

// s1[k] for all 8 steps from constant cur1 (m1 recurrence is elementwise).
__global__ void enc1_spikes() {
    int t = blockIdx.x * blockDim.x + threadIdx.x;   // < 262144
    float c = g_cur1[t];
    float m = 0.0f;
#pragma unroll
    for (int k = 0; k < 8; k++) {
        float reset = (m - 1.0f > 0.0f) ? 1.0f : 0.0f;
        m = 0.9f * m + c - reset;
        g_s1[k*262144 + t] = (m - 1.0f > 0.0f) ? 1.0f : 0.0f;
    }
}

// m2 scan over k; emits spk_rec.
__global__ void enc2_scan() {
    int t = blockIdx.x * blockDim.x + threadIdx.x;   // < 131072
    float m = 0.0f;
#pragma unroll
    for (int k = 0; k < 8; k++) {
        float c = g_cur2[k*131072 + t];
        float reset = (m - 1.0f > 0.0f) ? 1.0f : 0.0f;
        m = 0.9f * m + c - reset;
        g_spk[k*131072 + t] = (m - 1.0f > 0.0f) ? 1.0f : 0.0f;
    }
}

// s3[j] for all 8 steps from constant cur3.
__global__ void dec1_spikes() {
    int t = blockIdx.x * blockDim.x + threadIdx.x;   // < 2097152
    float c = g_cur3[t];
    float m = 0.0f;
#pragma unroll
    for (int j = 0; j < 8; j++) {
        float reset = (m - 1.0f > 0.0f) ? 1.0f : 0.0f;
        m = 0.9f * m + c - reset;
        g_s3[j*2097152 + t] = (m - 1.0f > 0.0f) ? 1.0f : 0.0f;
    }
}

// m4 scan over j; writes mem_rec_1 then spk_rec_1. Vectorized float4.
__global__ void dec2_out(float* __restrict__ out) {
    int t = blockIdx.x * blockDim.x + threadIdx.x;   // < 1048576
    const float4* c4 = reinterpret_cast<const float4*>(g_cur4);
    float4* om = reinterpret_cast<float4*>(out);
    float4* os = om + 8388608;   // 33554432 floats
    int r = t >> 7, q = t & 127;
    float4 m = make_float4(0.f, 0.f, 0.f, 0.f);
#pragma unroll
    for (int j = 0; j < 8; j++) {
        float4 c = c4[(j*8192 + r)*128 + q];
        float4 rst;
        rst.x = (m.x - 20000.0f > 0.0f) ? 20000.0f : 0.0f;
        rst.y = (m.y - 20000.0f > 0.0f) ? 20000.0f : 0.0f;
        rst.z = (m.z - 20000.0f > 0.0f) ? 20000.0f : 0.0f;
        rst.w = (m.w - 20000.0f > 0.0f) ? 20000.0f : 0.0f;
        m.x = 0.9f*m.x + c.x - rst.x;
        m.y = 0.9f*m.y + c.y - rst.y;
        m.z = 0.9f*m.z + c.z - rst.z;
        m.w = 0.9f*m.w + c.w - rst.w;
        int oidx = j*1048576 + r*128 + q;
        om[oidx] = m;
        float4 s;
        s.x = (m.x - 20000.0f > 0.0f) ? 1.0f : 0.0f;
        s.y = (m.y - 20000.0f > 0.0f) ? 1.0f : 0.0f;
        s.z = (m.z - 20000.0f > 0.0f) ? 1.0f : 0.0f;
        s.w = (m.w - 20000.0f > 0.0f) ? 1.0f : 0.0f;
        os[oidx] = s;
    }
}

extern "C" void kernel_launch(void* const* d_in, const int* in_sizes, int n_in,
                              void* d_out, int out_size) {
    const float* x  = (const float*)d_in[0];
    const float* W1 = (const float*)d_in[1];
    const float* b1 = (const float*)d_in[2];
    const float* W2 = (const float*)d_in[3];
    const float* b2 = (const float*)d_in[4];
    const float* W3 = (const float*)d_in[5];
    const float* b3 = (const float*)d_in[6];
    const float* W4 = (const float*)d_in[7];
    const float* b4 = (const float*)d_in[8];

    float *cur1, *s1, *cur2, *spk, *cur3, *s3, *cur4;
    cudaGetSymbolAddress((void**)&cur1, g_cur1);
    cudaGetSymbolAddress((void**)&s1,   g_s1);
    cudaGetSymbolAddress((void**)&cur2, g_cur2);
    cudaGetSymbolAddress((void**)&spk,  g_spk);
    cudaGetSymbolAddress((void**)&cur3, g_cur3);
    cudaGetSymbolAddress((void**)&s3,   g_s3);
    cudaGetSymbolAddress((void**)&cur4, g_cur4);

    // G1: cur1 = x @ W1^T + b1   [1024,256], K=512
    sgemm_bt<<<dim3(256/BN, 1024/BM), 256>>>(x, W1, b1, cur1, 1024, 256, 512);
    // E1: s1 for all steps
    enc1_spikes<<<262144/256, 256>>>();
    // G2: cur2 = s1 @ W2^T + b2  [8192,128], K=256
    sgemm_bt<<<dim3(128/BN, 8192/BM), 256>>>(s1, W2, b2, cur2, 8192, 128, 256);
    // E2: m2 scan -> spk_rec
    enc2_scan<<<131072/256, 256>>>();
    // G3: cur3 = spk @ W3^T + b3 [8192,256], K=128
    sgemm_bt<<<dim3(256/BN, 8192/BM), 256>>>(spk, W3, b3, cur3, 8192, 256, 128);
    // E3: s3 for all steps
    dec1_spikes<<<2097152/256, 256>>>();
    // G4: cur4 = s3 @ W4^T + b4  [65536,512], K=256  (dominant)
    sgemm_bt<<<dim3(512/BN, 65536/BM), 256>>>(s3, W4, b4, cur4, 65536, 512, 256);
    // E4: m4 scan + outputs
    dec2_out<<<1048576/256, 256>>>((float*)d_out);
}

// round 4
// speedup vs baseline: 3.8252x; 3.8252x over previous
#include <cuda_runtime.h>
#include <cuda_bf16.h>
#include <cstdint>

// ---------------------------------------------------------------------------
// Net_9560597201379 : SNN encoder/decoder.
// HMMA (mma.sync m16n8k16 bf16) with split weights:
//   G2/G3 (feed spike thresholds): 3-way split  -> fp32-level accuracy
//   G4    (feeds output mem only): 2-way split  -> ~1e-4 rel, dominant GEMM
// Spike activations are exactly {0,1} in bf16.
// ---------------------------------------------------------------------------

__device__ float          g_cur1[1024*256];
__device__ __nv_bfloat16  g_s1  [8*1024*256];
__device__ float          g_cur2[8*1024*128];
__device__ __nv_bfloat16  g_spk [8*1024*128];
__device__ float          g_cur3[8*1024*256];
__device__ __nv_bfloat16  g_s3  [8*8192*256];
__device__ float          g_cur4[8*8192*512];
__device__ __nv_bfloat16  g_w2hi[128*256], g_w2mi[128*256], g_w2lo[128*256];
__device__ __nv_bfloat16  g_w3hi[256*128], g_w3mi[256*128], g_w3lo[256*128];
__device__ __nv_bfloat16  g_w4hi[512*256], g_w4lo[512*256];

// ===================== helpers =============================================

__device__ __forceinline__ uint32_t smem_u32(const void* p) {
    uint32_t a;
    asm("{ .reg .u64 t; cvta.to.shared.u64 t, %1; cvt.u32.u64 %0, t; }"
        : "=r"(a) : "l"(p));
    return a;
}

__device__ __forceinline__ void cp16(uint32_t s, const void* g) {
    asm volatile("cp.async.cg.shared.global [%0], [%1], 16;" :: "r"(s), "l"(g));
}
__device__ __forceinline__ void cp_commit() {
    asm volatile("cp.async.commit_group;");
}
template <int N> __device__ __forceinline__ void cp_wait() {
    asm volatile("cp.async.wait_group %0;" :: "n"(N));
}

__device__ __forceinline__ void mma16816(float* d, const uint32_t* a,
                                         uint32_t b0, uint32_t b1) {
    asm volatile(
        "mma.sync.aligned.m16n8k16.row.col.f32.bf16.bf16.f32 "
        "{%0,%1,%2,%3}, {%4,%5,%6,%7}, {%8,%9}, {%0,%1,%2,%3};"
        : "+f"(d[0]), "+f"(d[1]), "+f"(d[2]), "+f"(d[3])
        : "r"(a[0]), "r"(a[1]), "r"(a[2]), "r"(a[3]), "r"(b0), "r"(b1));
}

// ===================== HMMA GEMM (templated over #B splits) ================
// C[M,N] = A[M,K] @ (sum_i B_i)[N,K]^T + bias.  M%128, N%128, K%64 == 0.
// grid = (N/128, M/128), block = 256.  Double-buffered cp.async, BK=64.

static const int ROWB = 144;              // bytes per smem row (72 bf16, padded)
static const int MATB = 128 * ROWB;       // 18432 B per matrix tile

template <int NB>
__global__ __launch_bounds__(256, 2) void mma_gemm_split(
    const __nv_bfloat16* __restrict__ A,
    const __nv_bfloat16* __restrict__ B0,
    const __nv_bfloat16* __restrict__ B1,
    const __nv_bfloat16* __restrict__ B2,
    const float* __restrict__ bias,
    float* __restrict__ C, int M, int N, int K)
{
    constexpr int STAGEB = (1 + NB) * MATB;
    extern __shared__ char sm[];
    const uint32_t sb = smem_u32(sm);
    const int tid = threadIdx.x, wid = tid >> 5, lane = tid & 31;
    const int bx = blockIdx.x, by = blockIdx.y;
    const int g = lane >> 2, tig = lane & 3;
    const int wm = (wid >> 2) * 64, wn = (wid & 3) * 32;

    const __nv_bfloat16* Ab = A + (size_t)(by * 128) * K;
    const __nv_bfloat16* Bb[NB];
    Bb[0] = B0 + (size_t)(bx * 128) * K;
    if (NB > 1) Bb[1] = B1 + (size_t)(bx * 128) * K;
    if (NB > 2) Bb[2] = B2 + (size_t)(bx * 128) * K;

    const int lrow = tid >> 3;            // base row
    const int lcg  = (tid & 7) * 8;       // col in elements

    float acc[4][4][4];
#pragma unroll
    for (int i = 0; i < 4; i++)
#pragma unroll
        for (int j = 0; j < 4; j++)
#pragma unroll
            for (int q = 0; q < 4; q++) acc[i][j][q] = 0.0f;

    const int nchunk = K >> 6;

    auto load_stage = [&](int c, int s) {
        const int k0 = c * 64;
        uint32_t base = sb + s * STAGEB;
#pragma unroll
        for (int i = 0; i < 4; i++) {
            int row = lrow + i * 32;
            uint32_t so = base + row * ROWB + lcg * 2;
            cp16(so, Ab + (size_t)row * K + k0 + lcg);
#pragma unroll
            for (int b = 0; b < NB; b++)
                cp16(so + (b + 1) * MATB, Bb[b] + (size_t)row * K + k0 + lcg);
        }
        cp_commit();
    };

    load_stage(0, 0);

    for (int c = 0; c < nchunk; c++) {
        if (c + 1 < nchunk) { load_stage(c + 1, (c + 1) & 1); cp_wait<1>(); }
        else                { cp_wait<0>(); }
        __syncthreads();

        const char* As = sm + (c & 1) * STAGEB;

#pragma unroll
        for (int kk = 0; kk < 4; kk++) {
            const int kb = (kk * 16 + tig * 2) * 2;   // byte offset in row
            uint32_t a[4][4];
#pragma unroll
            for (int mt = 0; mt < 4; mt++) {
                const char* p = As + (wm + mt * 16 + g) * ROWB + kb;
                a[mt][0] = *reinterpret_cast<const uint32_t*>(p);
                a[mt][1] = *reinterpret_cast<const uint32_t*>(p + 8 * ROWB);
                a[mt][2] = *reinterpret_cast<const uint32_t*>(p + 16);
                a[mt][3] = *reinterpret_cast<const uint32_t*>(p + 8 * ROWB + 16);
            }
#pragma unroll
            for (int nt = 0; nt < 4; nt++) {
                const int rowoff = (wn + nt * 8 + g) * ROWB + kb;
#pragma unroll
                for (int b = 0; b < NB; b++) {
                    const char* pb = As + (b + 1) * MATB + rowoff;
                    uint32_t b0 = *reinterpret_cast<const uint32_t*>(pb);
                    uint32_t b1 = *reinterpret_cast<const uint32_t*>(pb + 16);
#pragma unroll
                    for (int mt = 0; mt < 4; mt++)
                        mma16816(acc[mt][nt], a[mt], b0, b1);
                }
            }
        }
        __syncthreads();
    }

    // ---- epilogue: bias + store fp32 ----
#pragma unroll
    for (int mt = 0; mt < 4; mt++) {
#pragma unroll
        for (int nt = 0; nt < 4; nt++) {
            int row = by * 128 + wm + mt * 16 + g;
            int col = bx * 128 + wn + nt * 8 + tig * 2;
            float bv0 = bias[col], bv1 = bias[col + 1];
            float2 v0 = make_float2(acc[mt][nt][0] + bv0, acc[mt][nt][1] + bv1);
            float2 v1 = make_float2(acc[mt][nt][2] + bv0, acc[mt][nt][3] + bv1);
            *reinterpret_cast<float2*>(C + (size_t)row * N + col)       = v0;
            *reinterpret_cast<float2*>(C + (size_t)(row + 8) * N + col) = v1;
        }
    }
}

// ===================== fp32 scalar GEMM (G1 only) ==========================

#define BM 128
#define BN 128
#define BK 8
#define TM 8
#define TN 8

__device__ __forceinline__ void ffma2(unsigned long long& d,
                                      unsigned long long a,
                                      unsigned long long b) {
    asm("fma.rn.f32x2 %0, %1, %2, %0;" : "+l"(d) : "l"(a), "l"(b));
}

__global__ __launch_bounds__(256, 2) void sgemm_bt(
    const float* __restrict__ A, const float* __restrict__ B,
    const float* __restrict__ bias, float* __restrict__ C,
    int M, int N, int K)
{
    __shared__ float  As[BK][BM];
    __shared__ float2 Bs[BK][BN];

    const int tid = threadIdx.x;
    const int bx = blockIdx.x, by = blockIdx.y;
    const int lRow = tid >> 1;
    const int lCol = (tid & 1) * 4;
    const float* Ab = A + (size_t)by * BM * K;
    const float* Bb = B + (size_t)bx * BN * K;
    const int tr = (tid >> 4) * TM;
    const int tc = (tid & 15) * TN;

    unsigned long long acc[TM/2][TN];
#pragma unroll
    for (int i = 0; i < TM/2; i++)
#pragma unroll
        for (int j = 0; j < TN; j++) acc[i][j] = 0ull;

    for (int k0 = 0; k0 < K; k0 += BK) {
        float4 a4 = *reinterpret_cast<const float4*>(Ab + (size_t)lRow * K + k0 + lCol);
        As[lCol+0][lRow] = a4.x; As[lCol+1][lRow] = a4.y;
        As[lCol+2][lRow] = a4.z; As[lCol+3][lRow] = a4.w;
        float4 b4 = *reinterpret_cast<const float4*>(Bb + (size_t)lRow * K + k0 + lCol);
        Bs[lCol+0][lRow] = make_float2(b4.x, b4.x);
        Bs[lCol+1][lRow] = make_float2(b4.y, b4.y);
        Bs[lCol+2][lRow] = make_float2(b4.z, b4.z);
        Bs[lCol+3][lRow] = make_float2(b4.w, b4.w);
        __syncthreads();
#pragma unroll
        for (int kk = 0; kk < BK; kk++) {
            unsigned long long a2[TM/2], b2[TN];
#pragma unroll
            for (int i = 0; i < TM/2; i++)
                a2[i] = *reinterpret_cast<const unsigned long long*>(&As[kk][tr + 2*i]);
#pragma unroll
            for (int j = 0; j < TN; j++)
                b2[j] = *reinterpret_cast<const unsigned long long*>(&Bs[kk][tc + j]);
#pragma unroll
            for (int i = 0; i < TM/2; i++)
#pragma unroll
                for (int j = 0; j < TN; j++)
                    ffma2(acc[i][j], a2[i], b2[j]);
        }
        __syncthreads();
    }

    float bsv[TN];
#pragma unroll
    for (int j = 0; j < TN; j++) bsv[j] = bias[bx*BN + tc + j];
#pragma unroll
    for (int i = 0; i < TM/2; i++) {
#pragma unroll
        for (int h = 0; h < 2; h++) {
            int m = by*BM + tr + 2*i + h;
            float v[TN];
#pragma unroll
            for (int j = 0; j < TN; j++) {
                unsigned int u = h ? (unsigned int)(acc[i][j] >> 32)
                                   : (unsigned int)(acc[i][j] & 0xffffffffull);
                v[j] = __uint_as_float(u) + bsv[j];
            }
            float* Crow = C + (size_t)m * N + bx*BN + tc;
            *reinterpret_cast<float4*>(Crow)     = make_float4(v[0],v[1],v[2],v[3]);
            *reinterpret_cast<float4*>(Crow + 4) = make_float4(v[4],v[5],v[6],v[7]);
        }
    }
}

// ===================== elementwise kernels =================================

__global__ void split2_w(const float* __restrict__ W, __nv_bfloat16* __restrict__ hi,
                         __nv_bfloat16* __restrict__ lo, int n) {
    int i = blockIdx.x * blockDim.x + threadIdx.x;
    if (i < n) {
        float w = W[i];
        __nv_bfloat16 h = __float2bfloat16(w);
        hi[i] = h;
        lo[i] = __float2bfloat16(w - __bfloat162float(h));
    }
}

__global__ void split3_w(const float* __restrict__ W, __nv_bfloat16* __restrict__ hi,
                         __nv_bfloat16* __restrict__ mi, __nv_bfloat16* __restrict__ lo,
                         int n) {
    int i = blockIdx.x * blockDim.x + threadIdx.x;
    if (i < n) {
        float w = W[i];
        __nv_bfloat16 h = __float2bfloat16(w);
        float r1 = w - __bfloat162float(h);
        __nv_bfloat16 m = __float2bfloat16(r1);
        float r2 = r1 - __bfloat162float(m);
        hi[i] = h; mi[i] = m; lo[i] = __float2bfloat16(r2);
    }
}

__global__ void enc1_spikes() {
    int t = blockIdx.x * blockDim.x + threadIdx.x;   // < 262144
    float c = g_cur1[t];
    float m = 0.0f;
#pragma unroll
    for (int k = 0; k < 8; k++) {
        float reset = (m - 1.0f > 0.0f) ? 1.0f : 0.0f;
        m = 0.9f * m + c - reset;
        g_s1[k*262144 + t] = __float2bfloat16((m - 1.0f > 0.0f) ? 1.0f : 0.0f);
    }
}

__global__ void enc2_scan() {
    int t = blockIdx.x * blockDim.x + threadIdx.x;   // < 131072
    float m = 0.0f;
#pragma unroll
    for (int k = 0; k < 8; k++) {
        float c = g_cur2[k*131072 + t];
        float reset = (m - 1.0f > 0.0f) ? 1.0f : 0.0f;
        m = 0.9f * m + c - reset;
        g_spk[k*131072 + t] = __float2bfloat16((m - 1.0f > 0.0f) ? 1.0f : 0.0f);
    }
}

__global__ void dec1_spikes() {
    int t = blockIdx.x * blockDim.x + threadIdx.x;   // < 2097152
    float c = g_cur3[t];
    float m = 0.0f;
#pragma unroll
    for (int j = 0; j < 8; j++) {
        float reset = (m - 1.0f > 0.0f) ? 1.0f : 0.0f;
        m = 0.9f * m + c - reset;
        g_s3[j*2097152 + t] = __float2bfloat16((m - 1.0f > 0.0f) ? 1.0f : 0.0f);
    }
}

__global__ void dec2_out(float* __restrict__ out) {
    int t = blockIdx.x * blockDim.x + threadIdx.x;   // < 1048576
    const float4* c4 = reinterpret_cast<const float4*>(g_cur4);
    float4* om = reinterpret_cast<float4*>(out);
    float4* os = om + 8388608;
    int r = t >> 7, q = t & 127;
    float4 m = make_float4(0.f, 0.f, 0.f, 0.f);
#pragma unroll
    for (int j = 0; j < 8; j++) {
        float4 c = c4[(j*8192 + r)*128 + q];
        float4 rst;
        rst.x = (m.x - 20000.0f > 0.0f) ? 20000.0f : 0.0f;
        rst.y = (m.y - 20000.0f > 0.0f) ? 20000.0f : 0.0f;
        rst.z = (m.z - 20000.0f > 0.0f) ? 20000.0f : 0.0f;
        rst.w = (m.w - 20000.0f > 0.0f) ? 20000.0f : 0.0f;
        m.x = 0.9f*m.x + c.x - rst.x;
        m.y = 0.9f*m.y + c.y - rst.y;
        m.z = 0.9f*m.z + c.z - rst.z;
        m.w = 0.9f*m.w + c.w - rst.w;
        int oidx = j*1048576 + r*128 + q;
        om[oidx] = m;
        float4 s;
        s.x = (m.x - 20000.0f > 0.0f) ? 1.0f : 0.0f;
        s.y = (m.y - 20000.0f > 0.0f) ? 1.0f : 0.0f;
        s.z = (m.z - 20000.0f > 0.0f) ? 1.0f : 0.0f;
        s.w = (m.w - 20000.0f > 0.0f) ? 1.0f : 0.0f;
        os[oidx] = s;
    }
}

// ===================== launch ==============================================

extern "C" void kernel_launch(void* const* d_in, const int* in_sizes, int n_in,
                              void* d_out, int out_size) {
    const float* x  = (const float*)d_in[0];
    const float* W1 = (const float*)d_in[1];
    const float* b1 = (const float*)d_in[2];
    const float* W2 = (const float*)d_in[3];
    const float* b2 = (const float*)d_in[4];
    const float* W3 = (const float*)d_in[5];
    const float* b3 = (const float*)d_in[6];
    const float* W4 = (const float*)d_in[7];
    const float* b4 = (const float*)d_in[8];

    float *cur1, *cur2, *cur3, *cur4;
    __nv_bfloat16 *s1, *spk, *s3;
    __nv_bfloat16 *w2h, *w2m, *w2l, *w3h, *w3m, *w3l, *w4h, *w4l;
    cudaGetSymbolAddress((void**)&cur1, g_cur1);
    cudaGetSymbolAddress((void**)&s1,   g_s1);
    cudaGetSymbolAddress((void**)&cur2, g_cur2);
    cudaGetSymbolAddress((void**)&spk,  g_spk);
    cudaGetSymbolAddress((void**)&cur3, g_cur3);
    cudaGetSymbolAddress((void**)&s3,   g_s3);
    cudaGetSymbolAddress((void**)&cur4, g_cur4);
    cudaGetSymbolAddress((void**)&w2h,  g_w2hi);
    cudaGetSymbolAddress((void**)&w2m,  g_w2mi);
    cudaGetSymbolAddress((void**)&w2l,  g_w2lo);
    cudaGetSymbolAddress((void**)&w3h,  g_w3hi);
    cudaGetSymbolAddress((void**)&w3m,  g_w3mi);
    cudaGetSymbolAddress((void**)&w3l,  g_w3lo);
    cudaGetSymbolAddress((void**)&w4h,  g_w4hi);
    cudaGetSymbolAddress((void**)&w4l,  g_w4lo);

    const int SMEM2 = 2 * 3 * MATB;   // 110592
    const int SMEM3 = 2 * 4 * MATB;   // 147456
    cudaFuncSetAttribute(mma_gemm_split<2>,
                         cudaFuncAttributeMaxDynamicSharedMemorySize, SMEM2);
    cudaFuncSetAttribute(mma_gemm_split<3>,
                         cudaFuncAttributeMaxDynamicSharedMemorySize, SMEM3);

    // weight splits (tiny)
    split3_w<<<(32768 + 255)/256, 256>>>(W2, w2h, w2m, w2l, 32768);
    split3_w<<<(32768 + 255)/256, 256>>>(W3, w3h, w3m, w3l, 32768);
    split2_w<<<(131072 + 255)/256, 256>>>(W4, w4h, w4l, 131072);

    // G1: cur1 = x @ W1^T + b1   [1024,256], K=512  (fp32)
    sgemm_bt<<<dim3(2, 8), 256>>>(x, W1, b1, cur1, 1024, 256, 512);
    enc1_spikes<<<262144/256, 256>>>();

    // G2: cur2 = s1 @ W2^T + b2  [8192,128], K=256  (3-split)
    mma_gemm_split<3><<<dim3(1, 64), 256, SMEM3>>>(s1, w2h, w2m, w2l, b2, cur2, 8192, 128, 256);
    enc2_scan<<<131072/256, 256>>>();

    // G3: cur3 = spk @ W3^T + b3 [8192,256], K=128  (3-split)
    mma_gemm_split<3><<<dim3(2, 64), 256, SMEM3>>>(spk, w3h, w3m, w3l, b3, cur3, 8192, 256, 128);
    dec1_spikes<<<2097152/256, 256>>>();

    // G4: cur4 = s3 @ W4^T + b4  [65536,512], K=256  (2-split, dominant)
    mma_gemm_split<2><<<dim3(4, 512), 256, SMEM2>>>(s3, w4h, w4l, nullptr, b4, cur4, 65536, 512, 256);

    // E4: m4 scan + outputs
    dec2_out<<<1048576/256, 256>>>((float*)d_out);
}

// round 6
// speedup vs baseline: 5.8077x; 1.5183x over previous
#include <cuda_runtime.h>
#include <cuda_bf16.h>
#include <cstdint>

// ---------------------------------------------------------------------------
// Net_9560597201379 : SNN encoder/decoder.
//   G1: fp32 FFMA GEMM, 64x64 tiles (bitwise-identical arithmetic to the
//       proven 128x128 version, but 64 CTAs instead of 16).
//   G2/G3: HMMA, 3-way-split weights (feed spike thresholds).
//   G4: HMMA 2-way split, fused with m4 scan + output stores.
// Spike activations are exactly {0,1} in bf16.
// ---------------------------------------------------------------------------

__device__ float          g_cur1[1024*256];
__device__ __nv_bfloat16  g_s1  [8*1024*256];
__device__ float          g_cur2[8*1024*128];
__device__ __nv_bfloat16  g_spk [8*1024*128];
__device__ float          g_cur3[8*1024*256];
__device__ __nv_bfloat16  g_s3  [8*8192*256];
__device__ __nv_bfloat16  g_w2hi[128*256], g_w2mi[128*256], g_w2lo[128*256];
__device__ __nv_bfloat16  g_w3hi[256*128], g_w3mi[256*128], g_w3lo[256*128];
__device__ __nv_bfloat16  g_w4hi[512*256], g_w4lo[512*256];

// ===================== helpers =============================================

__device__ __forceinline__ uint32_t smem_u32(const void* p) {
    uint32_t a;
    asm("{ .reg .u64 t; cvta.to.shared.u64 t, %1; cvt.u32.u64 %0, t; }"
        : "=r"(a) : "l"(p));
    return a;
}

__device__ __forceinline__ void cp16(uint32_t s, const void* g) {
    asm volatile("cp.async.cg.shared.global [%0], [%1], 16;" :: "r"(s), "l"(g));
}
__device__ __forceinline__ void cp_commit() {
    asm volatile("cp.async.commit_group;");
}
template <int N> __device__ __forceinline__ void cp_wait() {
    asm volatile("cp.async.wait_group %0;" :: "n"(N));
}

__device__ __forceinline__ void mma16816(float* d, const uint32_t* a,
                                         uint32_t b0, uint32_t b1) {
    asm volatile(
        "mma.sync.aligned.m16n8k16.row.col.f32.bf16.bf16.f32 "
        "{%0,%1,%2,%3}, {%4,%5,%6,%7}, {%8,%9}, {%0,%1,%2,%3};"
        : "+f"(d[0]), "+f"(d[1]), "+f"(d[2]), "+f"(d[3])
        : "r"(a[0]), "r"(a[1]), "r"(a[2]), "r"(a[3]), "r"(b0), "r"(b1));
}

__device__ __forceinline__ void ffma2(unsigned long long& d,
                                      unsigned long long a,
                                      unsigned long long b) {
    asm("fma.rn.f32x2 %0, %1, %2, %0;" : "+l"(d) : "l"(a), "l"(b));
}

static const int ROWB = 144;              // bytes per smem row (72 bf16, padded)
static const int MATB = 128 * ROWB;       // 18432 B per 128x64 matrix tile

// ===================== generic HMMA GEMM (G2/G3) ===========================
// C[M,N] = A[M,K] @ (sum_i B_i)[N,K]^T + bias.  grid=(N/128, M/128).

template <int NB>
__global__ __launch_bounds__(256, 2) void mma_gemm_split(
    const __nv_bfloat16* __restrict__ A,
    const __nv_bfloat16* __restrict__ B0,
    const __nv_bfloat16* __restrict__ B1,
    const __nv_bfloat16* __restrict__ B2,
    const float* __restrict__ bias,
    float* __restrict__ C, int M, int N, int K)
{
    constexpr int STAGEB = (1 + NB) * MATB;
    extern __shared__ char sm[];
    const uint32_t sb = smem_u32(sm);
    const int tid = threadIdx.x, wid = tid >> 5, lane = tid & 31;
    const int bx = blockIdx.x, by = blockIdx.y;
    const int g = lane >> 2, tig = lane & 3;
    const int wm = (wid >> 2) * 64, wn = (wid & 3) * 32;

    const __nv_bfloat16* Ab = A + (size_t)(by * 128) * K;
    const __nv_bfloat16* Bb[NB];
    Bb[0] = B0 + (size_t)(bx * 128) * K;
    if (NB > 1) Bb[1] = B1 + (size_t)(bx * 128) * K;
    if (NB > 2) Bb[2] = B2 + (size_t)(bx * 128) * K;

    const int lrow = tid >> 3;
    const int lcg  = (tid & 7) * 8;

    float acc[4][4][4];
#pragma unroll
    for (int i = 0; i < 4; i++)
#pragma unroll
        for (int j = 0; j < 4; j++)
#pragma unroll
            for (int q = 0; q < 4; q++) acc[i][j][q] = 0.0f;

    const int nchunk = K >> 6;

    auto load_stage = [&](int c, int s) {
        const int k0 = c * 64;
        uint32_t base = sb + s * STAGEB;
#pragma unroll
        for (int i = 0; i < 4; i++) {
            int row = lrow + i * 32;
            uint32_t so = base + row * ROWB + lcg * 2;
            cp16(so, Ab + (size_t)row * K + k0 + lcg);
#pragma unroll
            for (int b = 0; b < NB; b++)
                cp16(so + (b + 1) * MATB, Bb[b] + (size_t)row * K + k0 + lcg);
        }
        cp_commit();
    };

    load_stage(0, 0);

    for (int c = 0; c < nchunk; c++) {
        if (c + 1 < nchunk) { load_stage(c + 1, (c + 1) & 1); cp_wait<1>(); }
        else                { cp_wait<0>(); }
        __syncthreads();

        const char* As = sm + (c & 1) * STAGEB;

#pragma unroll
        for (int kk = 0; kk < 4; kk++) {
            const int kb = (kk * 16 + tig * 2) * 2;
            uint32_t a[4][4];
#pragma unroll
            for (int mt = 0; mt < 4; mt++) {
                const char* p = As + (wm + mt * 16 + g) * ROWB + kb;
                a[mt][0] = *reinterpret_cast<const uint32_t*>(p);
                a[mt][1] = *reinterpret_cast<const uint32_t*>(p + 8 * ROWB);
                a[mt][2] = *reinterpret_cast<const uint32_t*>(p + 16);
                a[mt][3] = *reinterpret_cast<const uint32_t*>(p + 8 * ROWB + 16);
            }
#pragma unroll
            for (int nt = 0; nt < 4; nt++) {
                const int rowoff = (wn + nt * 8 + g) * ROWB + kb;
#pragma unroll
                for (int b = 0; b < NB; b++) {
                    const char* pb = As + (b + 1) * MATB + rowoff;
                    uint32_t b0 = *reinterpret_cast<const uint32_t*>(pb);
                    uint32_t b1 = *reinterpret_cast<const uint32_t*>(pb + 16);
#pragma unroll
                    for (int mt = 0; mt < 4; mt++)
                        mma16816(acc[mt][nt], a[mt], b0, b1);
                }
            }
        }
        __syncthreads();
    }

#pragma unroll
    for (int mt = 0; mt < 4; mt++) {
#pragma unroll
        for (int nt = 0; nt < 4; nt++) {
            int row = by * 128 + wm + mt * 16 + g;
            int col = bx * 128 + wn + nt * 8 + tig * 2;
            float bv0 = bias[col], bv1 = bias[col + 1];
            float2 v0 = make_float2(acc[mt][nt][0] + bv0, acc[mt][nt][1] + bv1);
            float2 v1 = make_float2(acc[mt][nt][2] + bv0, acc[mt][nt][3] + bv1);
            *reinterpret_cast<float2*>(C + (size_t)row * N + col)       = v0;
            *reinterpret_cast<float2*>(C + (size_t)(row + 8) * N + col) = v1;
        }
    }
}

// ===================== fused G4 + m4 scan + output =========================
// grid = (512/64, 8192/128) = (8, 64), block = 256 (8 warps 4x2, warp 32x32).
// B (both splits, full K=256) resident in smem; A streamed double-buffered.

static const int F_SBB  = 9216;               // 64 rows * 144 B per B chunk tile
static const int F_SBA  = 8 * F_SBB;          // 73728: B = 2 mats x 4 chunks
static const int F_SMEM = F_SBA + 2 * MATB;   // + A double stage = 110592

__global__ __launch_bounds__(256, 2) void gemm4_fused(
    const __nv_bfloat16* __restrict__ A,      // s3 [65536, 256]
    const __nv_bfloat16* __restrict__ B0,     // w4hi [512, 256]
    const __nv_bfloat16* __restrict__ B1,     // w4lo
    const float* __restrict__ bias,
    float* __restrict__ out)                  // mem @0, spk @ +33554432
{
    extern __shared__ char sm[];
    const uint32_t sb = smem_u32(sm);
    const int tid = threadIdx.x, wid = tid >> 5, lane = tid & 31;
    const int bx = blockIdx.x, by = blockIdx.y;
    const int g = lane >> 2, tig = lane & 3;
    const int wm = (wid >> 1) * 32, wn = (wid & 1) * 32;

    // ---- resident B load: 2 matrices x 64 rows x 256 cols ----
    {
        const __nv_bfloat16* Bsrc[2] = { B0 + (size_t)(bx * 64) * 256,
                                         B1 + (size_t)(bx * 64) * 256 };
#pragma unroll
        for (int b = 0; b < 2; b++)
#pragma unroll
            for (int i = 0; i < 8; i++) {
                int w = tid + i * 256;            // 0..2047
                int row = w >> 5, kcg = (w & 31) * 8;
                uint32_t dst = sb + (uint32_t)((b * 4 + (kcg >> 6)) * F_SBB +
                                               row * ROWB + (kcg & 63) * 2);
                cp16(dst, Bsrc[b] + (size_t)row * 256 + kcg);
            }
    }

    const int lrow = tid >> 3;
    const int lcg  = (tid & 7) * 8;
    auto load_stageA = [&](int gc) {
        int j = gc >> 2, kc = gc & 3;
        const __nv_bfloat16* Ab = A + (size_t)(j * 8192 + by * 128) * 256 + kc * 64;
        uint32_t base = sb + (uint32_t)(F_SBA + (gc & 1) * MATB);
#pragma unroll
        for (int i = 0; i < 4; i++) {
            int row = lrow + i * 32;
            cp16(base + row * ROWB + lcg * 2, Ab + (size_t)row * 256 + lcg);
        }
        cp_commit();
    };

    load_stageA(0);   // group 0 = {B + A0}, then one group per stage

    float bv[4][2];
#pragma unroll
    for (int nt = 0; nt < 4; nt++) {
        int col = bx * 64 + wn + nt * 8 + tig * 2;
        bv[nt][0] = bias[col]; bv[nt][1] = bias[col + 1];
    }

    float acc[2][4][4], m4[2][4][4];
#pragma unroll
    for (int i = 0; i < 2; i++)
#pragma unroll
        for (int j = 0; j < 4; j++)
#pragma unroll
            for (int q = 0; q < 4; q++) { acc[i][j][q] = 0.0f; m4[i][j][q] = 0.0f; }

    for (int gc = 0; gc < 32; gc++) {
        if (gc + 1 < 32) { load_stageA(gc + 1); cp_wait<1>(); }
        else             { cp_wait<0>(); }
        __syncthreads();

        const char* As = sm + F_SBA + (gc & 1) * MATB;
        const int kc = gc & 3;

#pragma unroll
        for (int kk = 0; kk < 4; kk++) {
            const int kb = (kk * 16 + tig * 2) * 2;
            uint32_t a[2][4];
#pragma unroll
            for (int mt = 0; mt < 2; mt++) {
                const char* p = As + (wm + mt * 16 + g) * ROWB + kb;
                a[mt][0] = *reinterpret_cast<const uint32_t*>(p);
                a[mt][1] = *reinterpret_cast<const uint32_t*>(p + 8 * ROWB);
                a[mt][2] = *reinterpret_cast<const uint32_t*>(p + 16);
                a[mt][3] = *reinterpret_cast<const uint32_t*>(p + 8 * ROWB + 16);
            }
#pragma unroll
            for (int nt = 0; nt < 4; nt++) {
                const int rowoff = (wn + nt * 8 + g) * ROWB + kb;
#pragma unroll
                for (int b = 0; b < 2; b++) {
                    const char* pb = sm + (b * 4 + kc) * F_SBB + rowoff;
                    uint32_t b0 = *reinterpret_cast<const uint32_t*>(pb);
                    uint32_t b1 = *reinterpret_cast<const uint32_t*>(pb + 16);
#pragma unroll
                    for (int mt = 0; mt < 2; mt++)
                        mma16816(acc[mt][nt], a[mt], b0, b1);
                }
            }
        }
        __syncthreads();

        if ((gc & 3) == 3) {
            const int j = gc >> 2;
#pragma unroll
            for (int mt = 0; mt < 2; mt++) {
#pragma unroll
                for (int nt = 0; nt < 4; nt++) {
                    int r0  = by * 128 + wm + mt * 16 + g;
                    int col = bx * 64 + wn + nt * 8 + tig * 2;
#pragma unroll
                    for (int h = 0; h < 2; h++) {
                        float c0 = acc[mt][nt][2*h]   + bv[nt][0];
                        float c1 = acc[mt][nt][2*h+1] + bv[nt][1];
                        float m0 = m4[mt][nt][2*h], m1 = m4[mt][nt][2*h+1];
                        float rst0 = (m0 - 20000.0f > 0.0f) ? 20000.0f : 0.0f;
                        float rst1 = (m1 - 20000.0f > 0.0f) ? 20000.0f : 0.0f;
                        m0 = 0.9f * m0 + c0 - rst0;
                        m1 = 0.9f * m1 + c1 - rst1;
                        m4[mt][nt][2*h] = m0; m4[mt][nt][2*h+1] = m1;
                        size_t base = ((size_t)(j * 8192 + r0 + h * 8)) * 512 + col;
                        *reinterpret_cast<float2*>(out + base) = make_float2(m0, m1);
                        float s0 = (m0 - 20000.0f > 0.0f) ? 1.0f : 0.0f;
                        float s1 = (m1 - 20000.0f > 0.0f) ? 1.0f : 0.0f;
                        *reinterpret_cast<float2*>(out + 33554432 + base) =
                            make_float2(s0, s1);
                        acc[mt][nt][2*h] = 0.0f; acc[mt][nt][2*h+1] = 0.0f;
                    }
                }
            }
        }
    }
}

// ===================== fp32 GEMM, 64x64 tiles (G1) =========================
// Bitwise-identical FFMA chain to the proven sgemm_bt: per output element,
// strictly ascending k, fma.rn.f32x2, acc init 0, + bias at the end.
// grid = (N/64, M/64), block = 256.

__global__ __launch_bounds__(256) void sgemm64(
    const float* __restrict__ A, const float* __restrict__ B,
    const float* __restrict__ bias, float* __restrict__ C,
    int M, int N, int K)
{
    __shared__ float  As[16][68];
    __shared__ float2 Bs[16][68];

    const int tid = threadIdx.x;
    const int bx = blockIdx.x, by = blockIdx.y;
    const int lrow = tid >> 2;          // 0..63
    const int lk   = (tid & 3) * 4;     // 0,4,8,12
    const float* Ab = A + (size_t)(by * 64) * K;
    const float* Bb = B + (size_t)(bx * 64) * K;
    const int tr = (tid >> 4) * 4;      // 0..60
    const int tc = (tid & 15) * 4;      // 0..60

    unsigned long long acc[2][4];
#pragma unroll
    for (int i = 0; i < 2; i++)
#pragma unroll
        for (int j = 0; j < 4; j++) acc[i][j] = 0ull;

    for (int k0 = 0; k0 < K; k0 += 16) {
        float4 a4 = *reinterpret_cast<const float4*>(Ab + (size_t)lrow * K + k0 + lk);
        As[lk+0][lrow] = a4.x; As[lk+1][lrow] = a4.y;
        As[lk+2][lrow] = a4.z; As[lk+3][lrow] = a4.w;
        float4 b4 = *reinterpret_cast<const float4*>(Bb + (size_t)lrow * K + k0 + lk);
        Bs[lk+0][lrow] = make_float2(b4.x, b4.x);
        Bs[lk+1][lrow] = make_float2(b4.y, b4.y);
        Bs[lk+2][lrow] = make_float2(b4.z, b4.z);
        Bs[lk+3][lrow] = make_float2(b4.w, b4.w);
        __syncthreads();
#pragma unroll
        for (int kk = 0; kk < 16; kk++) {
            unsigned long long a2[2], b2[4];
#pragma unroll
            for (int i = 0; i < 2; i++)
                a2[i] = *reinterpret_cast<const unsigned long long*>(&As[kk][tr + 2*i]);
#pragma unroll
            for (int j = 0; j < 4; j++)
                b2[j] = *reinterpret_cast<const unsigned long long*>(&Bs[kk][tc + j]);
#pragma unroll
            for (int i = 0; i < 2; i++)
#pragma unroll
                for (int j = 0; j < 4; j++)
                    ffma2(acc[i][j], a2[i], b2[j]);
        }
        __syncthreads();
    }

    float bsv[4];
#pragma unroll
    for (int j = 0; j < 4; j++) bsv[j] = bias[bx*64 + tc + j];
#pragma unroll
    for (int i = 0; i < 2; i++) {
#pragma unroll
        for (int h = 0; h < 2; h++) {
            int row = by*64 + tr + 2*i + h;
            float v[4];
#pragma unroll
            for (int j = 0; j < 4; j++) {
                unsigned int u = h ? (unsigned int)(acc[i][j] >> 32)
                                   : (unsigned int)(acc[i][j] & 0xffffffffull);
                v[j] = __uint_as_float(u) + bsv[j];
            }
            *reinterpret_cast<float4*>(C + (size_t)row * N + bx*64 + tc) =
                make_float4(v[0], v[1], v[2], v[3]);
        }
    }
}

// ===================== elementwise kernels =================================

__global__ void split2_w(const float* __restrict__ W, __nv_bfloat16* __restrict__ hi,
                         __nv_bfloat16* __restrict__ lo, int n) {
    int i = blockIdx.x * blockDim.x + threadIdx.x;
    if (i < n) {
        float w = W[i];
        __nv_bfloat16 h = __float2bfloat16(w);
        hi[i] = h;
        lo[i] = __float2bfloat16(w - __bfloat162float(h));
    }
}

__global__ void split3_w(const float* __restrict__ W, __nv_bfloat16* __restrict__ hi,
                         __nv_bfloat16* __restrict__ mi, __nv_bfloat16* __restrict__ lo,
                         int n) {
    int i = blockIdx.x * blockDim.x + threadIdx.x;
    if (i < n) {
        float w = W[i];
        __nv_bfloat16 h = __float2bfloat16(w);
        float r1 = w - __bfloat162float(h);
        __nv_bfloat16 m = __float2bfloat16(r1);
        float r2 = r1 - __bfloat162float(m);
        hi[i] = h; mi[i] = m; lo[i] = __float2bfloat16(r2);
    }
}

__global__ void enc1_spikes() {
    int t = blockIdx.x * blockDim.x + threadIdx.x;   // < 262144
    float c = g_cur1[t];
    float m = 0.0f;
#pragma unroll
    for (int k = 0; k < 8; k++) {
        float reset = (m - 1.0f > 0.0f) ? 1.0f : 0.0f;
        m = 0.9f * m + c - reset;
        g_s1[k*262144 + t] = __float2bfloat16((m - 1.0f > 0.0f) ? 1.0f : 0.0f);
    }
}

__global__ void enc2_scan() {
    int t = blockIdx.x * blockDim.x + threadIdx.x;   // < 131072
    float m = 0.0f;
#pragma unroll
    for (int k = 0; k < 8; k++) {
        float c = g_cur2[k*131072 + t];
        float reset = (m - 1.0f > 0.0f) ? 1.0f : 0.0f;
        m = 0.9f * m + c - reset;
        g_spk[k*131072 + t] = __float2bfloat16((m - 1.0f > 0.0f) ? 1.0f : 0.0f);
    }
}

__global__ void dec1_spikes() {
    int t = blockIdx.x * blockDim.x + threadIdx.x;   // < 2097152
    float c = g_cur3[t];
    float m = 0.0f;
#pragma unroll
    for (int j = 0; j < 8; j++) {
        float reset = (m - 1.0f > 0.0f) ? 1.0f : 0.0f;
        m = 0.9f * m + c - reset;
        g_s3[j*2097152 + t] = __float2bfloat16((m - 1.0f > 0.0f) ? 1.0f : 0.0f);
    }
}

// ===================== launch ==============================================

extern "C" void kernel_launch(void* const* d_in, const int* in_sizes, int n_in,
                              void* d_out, int out_size) {
    const float* x  = (const float*)d_in[0];
    const float* W1 = (const float*)d_in[1];
    const float* b1 = (const float*)d_in[2];
    const float* W2 = (const float*)d_in[3];
    const float* b2 = (const float*)d_in[4];
    const float* W3 = (const float*)d_in[5];
    const float* b3 = (const float*)d_in[6];
    const float* W4 = (const float*)d_in[7];
    const float* b4 = (const float*)d_in[8];

    float *cur1, *cur2, *cur3;
    __nv_bfloat16 *s1, *spk, *s3;
    __nv_bfloat16 *w2h, *w2m, *w2l, *w3h, *w3m, *w3l, *w4h, *w4l;
    cudaGetSymbolAddress((void**)&cur1, g_cur1);
    cudaGetSymbolAddress((void**)&s1,   g_s1);
    cudaGetSymbolAddress((void**)&cur2, g_cur2);
    cudaGetSymbolAddress((void**)&spk,  g_spk);
    cudaGetSymbolAddress((void**)&cur3, g_cur3);
    cudaGetSymbolAddress((void**)&s3,   g_s3);
    cudaGetSymbolAddress((void**)&w2h,  g_w2hi);
    cudaGetSymbolAddress((void**)&w2m,  g_w2mi);
    cudaGetSymbolAddress((void**)&w2l,  g_w2lo);
    cudaGetSymbolAddress((void**)&w3h,  g_w3hi);
    cudaGetSymbolAddress((void**)&w3m,  g_w3mi);
    cudaGetSymbolAddress((void**)&w3l,  g_w3lo);
    cudaGetSymbolAddress((void**)&w4h,  g_w4hi);
    cudaGetSymbolAddress((void**)&w4l,  g_w4lo);

    const int SMEM3 = 2 * 4 * MATB;   // 147456
    cudaFuncSetAttribute(mma_gemm_split<3>,
                         cudaFuncAttributeMaxDynamicSharedMemorySize, SMEM3);
    cudaFuncSetAttribute(gemm4_fused,
                         cudaFuncAttributeMaxDynamicSharedMemorySize, F_SMEM);

    // weight splits (tiny)
    split3_w<<<(32768  + 255)/256, 256>>>(W2, w2h, w2m, w2l, 32768);
    split3_w<<<(32768  + 255)/256, 256>>>(W3, w3h, w3m, w3l, 32768);
    split2_w<<<(131072 + 255)/256, 256>>>(W4, w4h, w4l, 131072);

    // G1: cur1 = x @ W1^T + b1   [1024,256], K=512  (fp32, 64 CTAs)
    sgemm64<<<dim3(4, 16), 256>>>(x, W1, b1, cur1, 1024, 256, 512);
    enc1_spikes<<<262144/256, 256>>>();

    // G2: cur2 = s1 @ W2^T + b2  [8192,128], K=256  (3-split)
    mma_gemm_split<3><<<dim3(1, 64), 256, SMEM3>>>(s1, w2h, w2m, w2l, b2, cur2, 8192, 128, 256);
    enc2_scan<<<131072/256, 256>>>();

    // G3: cur3 = spk @ W3^T + b3 [8192,256], K=128  (3-split)
    mma_gemm_split<3><<<dim3(2, 64), 256, SMEM3>>>(spk, w3h, w3m, w3l, b3, cur3, 8192, 256, 128);
    dec1_spikes<<<2097152/256, 256>>>();

    // G4 fused with m4 scan + output writes
    gemm4_fused<<<dim3(8, 64), 256, F_SMEM>>>(s3, w4h, w4l, b4, (float*)d_out);
}

// round 7
// speedup vs baseline: 6.7664x; 1.1651x over previous
#include <cuda_runtime.h>
#include <cuda_bf16.h>
#include <cstdint>

// ---------------------------------------------------------------------------
// Net_9560597201379 : SNN encoder/decoder.
//   G1+enc1 fused: fp32 scalar-FMA GEMM (exact sequential-k chain), 64x32
//                  tiles, 128 CTAs, transposed smem; writes s1 spikes direct.
//   G2: HMMA 3-way-split W -> cur2 ; enc2 scan standalone (cross-k).
//   G3+dec1 fused: HMMA 3-way-split W, m3 scan in registers -> s3 direct.
//   G4 fused: HMMA 2-way split W4 + m4 scan + output stores.
// Spike activations are exactly {0,1} in bf16 (bits 0x3F80 / 0x0000).
// ---------------------------------------------------------------------------

__device__ __nv_bfloat16  g_s1  [8*1024*256];
__device__ float          g_cur2[8*1024*128];
__device__ __nv_bfloat16  g_spk [8*1024*128];
__device__ __nv_bfloat16  g_s3  [8*8192*256];
__device__ __nv_bfloat16  g_w2hi[128*256], g_w2mi[128*256], g_w2lo[128*256];
__device__ __nv_bfloat16  g_w3hi[256*128], g_w3mi[256*128], g_w3lo[256*128];
__device__ __nv_bfloat16  g_w4hi[512*256], g_w4lo[512*256];

// ===================== helpers =============================================

__device__ __forceinline__ uint32_t smem_u32(const void* p) {
    uint32_t a;
    asm("{ .reg .u64 t; cvta.to.shared.u64 t, %1; cvt.u32.u64 %0, t; }"
        : "=r"(a) : "l"(p));
    return a;
}

__device__ __forceinline__ void cp16(uint32_t s, const void* g) {
    asm volatile("cp.async.cg.shared.global [%0], [%1], 16;" :: "r"(s), "l"(g));
}
__device__ __forceinline__ void cp_commit() {
    asm volatile("cp.async.commit_group;");
}
template <int N> __device__ __forceinline__ void cp_wait() {
    asm volatile("cp.async.wait_group %0;" :: "n"(N));
}

__device__ __forceinline__ void mma16816(float* d, const uint32_t* a,
                                         uint32_t b0, uint32_t b1) {
    asm volatile(
        "mma.sync.aligned.m16n8k16.row.col.f32.bf16.bf16.f32 "
        "{%0,%1,%2,%3}, {%4,%5,%6,%7}, {%8,%9}, {%0,%1,%2,%3};"
        : "+f"(d[0]), "+f"(d[1]), "+f"(d[2]), "+f"(d[3])
        : "r"(a[0]), "r"(a[1]), "r"(a[2]), "r"(a[3]), "r"(b0), "r"(b1));
}

// spike pair -> packed bf16x2 bits (1.0f = 0x3F80, 0.0f = 0x0000)
__device__ __forceinline__ uint32_t spike_pack(float m0, float m1, float th) {
    uint32_t lo = (m0 - th > 0.0f) ? 0x3F80u : 0u;
    uint32_t hi = (m1 - th > 0.0f) ? 0x3F80u : 0u;
    return lo | (hi << 16);
}

static const int ROWB = 144;              // bytes per smem row (72 bf16, padded)
static const int MATB = 128 * ROWB;       // 18432 B per 128x64 matrix tile

// ===================== G1 + enc1 fused =====================================
// cur1 = x[1024,512] @ W1[256,512]^T + b1 ; s1[k] = enc-L1 spikes, k=0..7.
// Exact per-output chain: fma.rn ascending k, acc=0 init, +bias last.
// grid = (256/32, 1024/64) = (8,16) = 128 CTAs, block 256.

__global__ __launch_bounds__(256) void g1_enc1(
    const float* __restrict__ A, const float* __restrict__ B,
    const float* __restrict__ bias, __nv_bfloat16* __restrict__ S1)
{
    __shared__ float As[16][68];   // [k][row]
    __shared__ float Bs[16][36];   // [k][col]

    const int tid = threadIdx.x;
    const int bx = blockIdx.x, by = blockIdx.y;
    const int arow = tid >> 2, akq = (tid & 3) * 4;
    const int brow = tid >> 3, bkq = (tid & 7) * 2;
    const int tr = (tid >> 4) * 4, tc = (tid & 15) * 2;

    const float* Ab = A + (size_t)(by * 64) * 512;
    const float* Bb = B + (size_t)(bx * 32) * 512;

    float4 ar = *reinterpret_cast<const float4*>(Ab + arow * 512 + akq);
    float2 br = *reinterpret_cast<const float2*>(Bb + brow * 512 + bkq);

    float acc[4][2];
#pragma unroll
    for (int i = 0; i < 4; i++) { acc[i][0] = 0.0f; acc[i][1] = 0.0f; }

    for (int c = 0; c < 32; c++) {
        As[akq + 0][arow] = ar.x;
        As[akq + 1][arow] = ar.y;
        As[akq + 2][arow] = ar.z;
        As[akq + 3][arow] = ar.w;
        Bs[bkq + 0][brow] = br.x;
        Bs[bkq + 1][brow] = br.y;
        __syncthreads();
        if (c + 1 < 32) {
            ar = *reinterpret_cast<const float4*>(Ab + arow * 512 + (c + 1) * 16 + akq);
            br = *reinterpret_cast<const float2*>(Bb + brow * 512 + (c + 1) * 16 + bkq);
        }
#pragma unroll
        for (int kk = 0; kk < 16; kk++) {
            float4 av = *reinterpret_cast<const float4*>(&As[kk][tr]);
            float b0 = Bs[kk][tc], b1 = Bs[kk][tc + 1];
            acc[0][0] = fmaf(av.x, b0, acc[0][0]);
            acc[0][1] = fmaf(av.x, b1, acc[0][1]);
            acc[1][0] = fmaf(av.y, b0, acc[1][0]);
            acc[1][1] = fmaf(av.y, b1, acc[1][1]);
            acc[2][0] = fmaf(av.z, b0, acc[2][0]);
            acc[2][1] = fmaf(av.z, b1, acc[2][1]);
            acc[3][0] = fmaf(av.w, b0, acc[3][0]);
            acc[3][1] = fmaf(av.w, b1, acc[3][1]);
        }
        __syncthreads();
    }

    const int col = bx * 32 + tc;
    const float bv0 = bias[col], bv1 = bias[col + 1];
#pragma unroll
    for (int i = 0; i < 4; i++) {
        const int row = by * 64 + tr + i;
        float c0 = acc[i][0] + bv0;
        float c1 = acc[i][1] + bv1;
        float m0 = 0.0f, m1 = 0.0f;
        uint32_t* dst = reinterpret_cast<uint32_t*>(S1 + (size_t)row * 256 + col);
#pragma unroll
        for (int k = 0; k < 8; k++) {
            float r0 = (m0 - 1.0f > 0.0f) ? 1.0f : 0.0f;
            float r1 = (m1 - 1.0f > 0.0f) ? 1.0f : 0.0f;
            m0 = 0.9f * m0 + c0 - r0;
            m1 = 0.9f * m1 + c1 - r1;
            dst[k * 131072] = spike_pack(m0, m1, 1.0f);
        }
    }
}

// ===================== generic HMMA GEMM (G2 / G3+dec1) ====================
// C[M,N] = A[M,K] @ (sum_i B_i)[N,K]^T + bias.  grid=(N/128, M/128).
// DEC1: instead of storing C, run the 8-step m3 scan in registers and store
// spike bf16 pairs to S3[(j*8192+row)*256+col].

template <int NB, bool DEC1>
__global__ __launch_bounds__(256, 2) void mma_gemm_split(
    const __nv_bfloat16* __restrict__ A,
    const __nv_bfloat16* __restrict__ B0,
    const __nv_bfloat16* __restrict__ B1,
    const __nv_bfloat16* __restrict__ B2,
    const float* __restrict__ bias,
    float* __restrict__ C, __nv_bfloat16* __restrict__ S3,
    int M, int N, int K)
{
    constexpr int STAGEB = (1 + NB) * MATB;
    extern __shared__ char sm[];
    const uint32_t sb = smem_u32(sm);
    const int tid = threadIdx.x, wid = tid >> 5, lane = tid & 31;
    const int bx = blockIdx.x, by = blockIdx.y;
    const int g = lane >> 2, tig = lane & 3;
    const int wm = (wid >> 2) * 64, wn = (wid & 3) * 32;

    const __nv_bfloat16* Ab = A + (size_t)(by * 128) * K;
    const __nv_bfloat16* Bb[NB];
    Bb[0] = B0 + (size_t)(bx * 128) * K;
    if (NB > 1) Bb[1] = B1 + (size_t)(bx * 128) * K;
    if (NB > 2) Bb[2] = B2 + (size_t)(bx * 128) * K;

    const int lrow = tid >> 3;
    const int lcg  = (tid & 7) * 8;

    float acc[4][4][4];
#pragma unroll
    for (int i = 0; i < 4; i++)
#pragma unroll
        for (int j = 0; j < 4; j++)
#pragma unroll
            for (int q = 0; q < 4; q++) acc[i][j][q] = 0.0f;

    const int nchunk = K >> 6;

    auto load_stage = [&](int c, int s) {
        const int k0 = c * 64;
        uint32_t base = sb + s * STAGEB;
#pragma unroll
        for (int i = 0; i < 4; i++) {
            int row = lrow + i * 32;
            uint32_t so = base + row * ROWB + lcg * 2;
            cp16(so, Ab + (size_t)row * K + k0 + lcg);
#pragma unroll
            for (int b = 0; b < NB; b++)
                cp16(so + (b + 1) * MATB, Bb[b] + (size_t)row * K + k0 + lcg);
        }
        cp_commit();
    };

    load_stage(0, 0);

    for (int c = 0; c < nchunk; c++) {
        if (c + 1 < nchunk) { load_stage(c + 1, (c + 1) & 1); cp_wait<1>(); }
        else                { cp_wait<0>(); }
        __syncthreads();

        const char* As = sm + (c & 1) * STAGEB;

#pragma unroll
        for (int kk = 0; kk < 4; kk++) {
            const int kb = (kk * 16 + tig * 2) * 2;
            uint32_t a[4][4];
#pragma unroll
            for (int mt = 0; mt < 4; mt++) {
                const char* p = As + (wm + mt * 16 + g) * ROWB + kb;
                a[mt][0] = *reinterpret_cast<const uint32_t*>(p);
                a[mt][1] = *reinterpret_cast<const uint32_t*>(p + 8 * ROWB);
                a[mt][2] = *reinterpret_cast<const uint32_t*>(p + 16);
                a[mt][3] = *reinterpret_cast<const uint32_t*>(p + 8 * ROWB + 16);
            }
#pragma unroll
            for (int nt = 0; nt < 4; nt++) {
                const int rowoff = (wn + nt * 8 + g) * ROWB + kb;
#pragma unroll
                for (int b = 0; b < NB; b++) {
                    const char* pb = As + (b + 1) * MATB + rowoff;
                    uint32_t b0 = *reinterpret_cast<const uint32_t*>(pb);
                    uint32_t b1 = *reinterpret_cast<const uint32_t*>(pb + 16);
#pragma unroll
                    for (int mt = 0; mt < 4; mt++)
                        mma16816(acc[mt][nt], a[mt], b0, b1);
                }
            }
        }
        __syncthreads();
    }

#pragma unroll
    for (int mt = 0; mt < 4; mt++) {
#pragma unroll
        for (int nt = 0; nt < 4; nt++) {
            int row = by * 128 + wm + mt * 16 + g;
            int col = bx * 128 + wn + nt * 8 + tig * 2;
            float bv0 = bias[col], bv1 = bias[col + 1];
            if (DEC1) {
#pragma unroll
                for (int h = 0; h < 2; h++) {
                    float c0 = acc[mt][nt][2*h]   + bv0;
                    float c1 = acc[mt][nt][2*h+1] + bv1;
                    float m0 = 0.0f, m1 = 0.0f;
                    uint32_t* dst = reinterpret_cast<uint32_t*>(
                        S3 + (size_t)(row + h * 8) * 256 + col);
#pragma unroll
                    for (int j = 0; j < 8; j++) {
                        float r0 = (m0 - 1.0f > 0.0f) ? 1.0f : 0.0f;
                        float r1 = (m1 - 1.0f > 0.0f) ? 1.0f : 0.0f;
                        m0 = 0.9f * m0 + c0 - r0;
                        m1 = 0.9f * m1 + c1 - r1;
                        dst[j * 1048576] = spike_pack(m0, m1, 1.0f);
                    }
                }
            } else {
                float2 v0 = make_float2(acc[mt][nt][0] + bv0, acc[mt][nt][1] + bv1);
                float2 v1 = make_float2(acc[mt][nt][2] + bv0, acc[mt][nt][3] + bv1);
                *reinterpret_cast<float2*>(C + (size_t)row * N + col)       = v0;
                *reinterpret_cast<float2*>(C + (size_t)(row + 8) * N + col) = v1;
            }
        }
    }
}

// ===================== fused G4 + m4 scan + output =========================
// grid = (512/64, 8192/128) = (8, 64), block = 256 (8 warps 4x2, warp 32x32).

static const int F_SBB  = 9216;               // 64 rows * 144 B per B chunk tile
static const int F_SBA  = 8 * F_SBB;          // 73728: B = 2 mats x 4 chunks
static const int F_SMEM = F_SBA + 2 * MATB;   // + A double stage = 110592

__global__ __launch_bounds__(256, 2) void gemm4_fused(
    const __nv_bfloat16* __restrict__ A,      // s3 [65536, 256]
    const __nv_bfloat16* __restrict__ B0,     // w4hi [512, 256]
    const __nv_bfloat16* __restrict__ B1,     // w4lo
    const float* __restrict__ bias,
    float* __restrict__ out)                  // mem @0, spk @ +33554432
{
    extern __shared__ char sm[];
    const uint32_t sb = smem_u32(sm);
    const int tid = threadIdx.x, wid = tid >> 5, lane = tid & 31;
    const int bx = blockIdx.x, by = blockIdx.y;
    const int g = lane >> 2, tig = lane & 3;
    const int wm = (wid >> 1) * 32, wn = (wid & 1) * 32;

    {
        const __nv_bfloat16* Bsrc[2] = { B0 + (size_t)(bx * 64) * 256,
                                         B1 + (size_t)(bx * 64) * 256 };
#pragma unroll
        for (int b = 0; b < 2; b++)
#pragma unroll
            for (int i = 0; i < 8; i++) {
                int w = tid + i * 256;
                int row = w >> 5, kcg = (w & 31) * 8;
                uint32_t dst = sb + (uint32_t)((b * 4 + (kcg >> 6)) * F_SBB +
                                               row * ROWB + (kcg & 63) * 2);
                cp16(dst, Bsrc[b] + (size_t)row * 256 + kcg);
            }
    }

    const int lrow = tid >> 3;
    const int lcg  = (tid & 7) * 8;
    auto load_stageA = [&](int gc) {
        int j = gc >> 2, kc = gc & 3;
        const __nv_bfloat16* Ab = A + (size_t)(j * 8192 + by * 128) * 256 + kc * 64;
        uint32_t base = sb + (uint32_t)(F_SBA + (gc & 1) * MATB);
#pragma unroll
        for (int i = 0; i < 4; i++) {
            int row = lrow + i * 32;
            cp16(base + row * ROWB + lcg * 2, Ab + (size_t)row * 256 + lcg);
        }
        cp_commit();
    };

    load_stageA(0);

    float bv[4][2];
#pragma unroll
    for (int nt = 0; nt < 4; nt++) {
        int col = bx * 64 + wn + nt * 8 + tig * 2;
        bv[nt][0] = bias[col]; bv[nt][1] = bias[col + 1];
    }

    float acc[2][4][4], m4[2][4][4];
#pragma unroll
    for (int i = 0; i < 2; i++)
#pragma unroll
        for (int j = 0; j < 4; j++)
#pragma unroll
            for (int q = 0; q < 4; q++) { acc[i][j][q] = 0.0f; m4[i][j][q] = 0.0f; }

    for (int gc = 0; gc < 32; gc++) {
        if (gc + 1 < 32) { load_stageA(gc + 1); cp_wait<1>(); }
        else             { cp_wait<0>(); }
        __syncthreads();

        const char* As = sm + F_SBA + (gc & 1) * MATB;
        const int kc = gc & 3;

#pragma unroll
        for (int kk = 0; kk < 4; kk++) {
            const int kb = (kk * 16 + tig * 2) * 2;
            uint32_t a[2][4];
#pragma unroll
            for (int mt = 0; mt < 2; mt++) {
                const char* p = As + (wm + mt * 16 + g) * ROWB + kb;
                a[mt][0] = *reinterpret_cast<const uint32_t*>(p);
                a[mt][1] = *reinterpret_cast<const uint32_t*>(p + 8 * ROWB);
                a[mt][2] = *reinterpret_cast<const uint32_t*>(p + 16);
                a[mt][3] = *reinterpret_cast<const uint32_t*>(p + 8 * ROWB + 16);
            }
#pragma unroll
            for (int nt = 0; nt < 4; nt++) {
                const int rowoff = (wn + nt * 8 + g) * ROWB + kb;
#pragma unroll
                for (int b = 0; b < 2; b++) {
                    const char* pb = sm + (b * 4 + kc) * F_SBB + rowoff;
                    uint32_t b0 = *reinterpret_cast<const uint32_t*>(pb);
                    uint32_t b1 = *reinterpret_cast<const uint32_t*>(pb + 16);
#pragma unroll
                    for (int mt = 0; mt < 2; mt++)
                        mma16816(acc[mt][nt], a[mt], b0, b1);
                }
            }
        }
        __syncthreads();

        if ((gc & 3) == 3) {
            const int j = gc >> 2;
#pragma unroll
            for (int mt = 0; mt < 2; mt++) {
#pragma unroll
                for (int nt = 0; nt < 4; nt++) {
                    int r0  = by * 128 + wm + mt * 16 + g;
                    int col = bx * 64 + wn + nt * 8 + tig * 2;
#pragma unroll
                    for (int h = 0; h < 2; h++) {
                        float c0 = acc[mt][nt][2*h]   + bv[nt][0];
                        float c1 = acc[mt][nt][2*h+1] + bv[nt][1];
                        float m0 = m4[mt][nt][2*h], m1 = m4[mt][nt][2*h+1];
                        float rst0 = (m0 - 20000.0f > 0.0f) ? 20000.0f : 0.0f;
                        float rst1 = (m1 - 20000.0f > 0.0f) ? 20000.0f : 0.0f;
                        m0 = 0.9f * m0 + c0 - rst0;
                        m1 = 0.9f * m1 + c1 - rst1;
                        m4[mt][nt][2*h] = m0; m4[mt][nt][2*h+1] = m1;
                        size_t base = ((size_t)(j * 8192 + r0 + h * 8)) * 512 + col;
                        *reinterpret_cast<float2*>(out + base) = make_float2(m0, m1);
                        float s0 = (m0 - 20000.0f > 0.0f) ? 1.0f : 0.0f;
                        float s1 = (m1 - 20000.0f > 0.0f) ? 1.0f : 0.0f;
                        *reinterpret_cast<float2*>(out + 33554432 + base) =
                            make_float2(s0, s1);
                        acc[mt][nt][2*h] = 0.0f; acc[mt][nt][2*h+1] = 0.0f;
                    }
                }
            }
        }
    }
}

// ===================== split + scan kernels ================================

__global__ void split_all(const float* __restrict__ W2, const float* __restrict__ W3,
                          const float* __restrict__ W4) {
    int b = blockIdx.x;
    if (b < 128) {                              // W2 3-way
        int i = b * 256 + threadIdx.x;
        float w = W2[i];
        __nv_bfloat16 h = __float2bfloat16(w);
        float r1 = w - __bfloat162float(h);
        __nv_bfloat16 m = __float2bfloat16(r1);
        g_w2hi[i] = h; g_w2mi[i] = m;
        g_w2lo[i] = __float2bfloat16(r1 - __bfloat162float(m));
    } else if (b < 256) {                       // W3 3-way
        int i = (b - 128) * 256 + threadIdx.x;
        float w = W3[i];
        __nv_bfloat16 h = __float2bfloat16(w);
        float r1 = w - __bfloat162float(h);
        __nv_bfloat16 m = __float2bfloat16(r1);
        g_w3hi[i] = h; g_w3mi[i] = m;
        g_w3lo[i] = __float2bfloat16(r1 - __bfloat162float(m));
    } else {                                    // W4 2-way
        int i = (b - 256) * 256 + threadIdx.x;
        float w = W4[i];
        __nv_bfloat16 h = __float2bfloat16(w);
        g_w4hi[i] = h;
        g_w4lo[i] = __float2bfloat16(w - __bfloat162float(h));
    }
}

__global__ void enc2_scan() {
    int t = blockIdx.x * blockDim.x + threadIdx.x;   // < 131072
    float m = 0.0f;
#pragma unroll
    for (int k = 0; k < 8; k++) {
        float c = g_cur2[k*131072 + t];
        float reset = (m - 1.0f > 0.0f) ? 1.0f : 0.0f;
        m = 0.9f * m + c - reset;
        g_spk[k*131072 + t] = __float2bfloat16((m - 1.0f > 0.0f) ? 1.0f : 0.0f);
    }
}

// ===================== launch ==============================================

extern "C" void kernel_launch(void* const* d_in, const int* in_sizes, int n_in,
                              void* d_out, int out_size) {
    const float* x  = (const float*)d_in[0];
    const float* W1 = (const float*)d_in[1];
    const float* b1 = (const float*)d_in[2];
    const float* W2 = (const float*)d_in[3];
    const float* b2 = (const float*)d_in[4];
    const float* W3 = (const float*)d_in[5];
    const float* b3 = (const float*)d_in[6];
    const float* W4 = (const float*)d_in[7];
    const float* b4 = (const float*)d_in[8];

    float *cur2;
    __nv_bfloat16 *s1, *spk, *s3;
    __nv_bfloat16 *w2h, *w2m, *w2l, *w3h, *w3m, *w3l, *w4h, *w4l;
    cudaGetSymbolAddress((void**)&s1,   g_s1);
    cudaGetSymbolAddress((void**)&cur2, g_cur2);
    cudaGetSymbolAddress((void**)&spk,  g_spk);
    cudaGetSymbolAddress((void**)&s3,   g_s3);
    cudaGetSymbolAddress((void**)&w2h,  g_w2hi);
    cudaGetSymbolAddress((void**)&w2m,  g_w2mi);
    cudaGetSymbolAddress((void**)&w2l,  g_w2lo);
    cudaGetSymbolAddress((void**)&w3h,  g_w3hi);
    cudaGetSymbolAddress((void**)&w3m,  g_w3mi);
    cudaGetSymbolAddress((void**)&w3l,  g_w3lo);
    cudaGetSymbolAddress((void**)&w4h,  g_w4hi);
    cudaGetSymbolAddress((void**)&w4l,  g_w4lo);

    const int SMEM3 = 2 * 4 * MATB;   // 147456
    cudaFuncSetAttribute(mma_gemm_split<3,false>,
                         cudaFuncAttributeMaxDynamicSharedMemorySize, SMEM3);
    cudaFuncSetAttribute(mma_gemm_split<3,true>,
                         cudaFuncAttributeMaxDynamicSharedMemorySize, SMEM3);
    cudaFuncSetAttribute(gemm4_fused,
                         cudaFuncAttributeMaxDynamicSharedMemorySize, F_SMEM);

    // weight splits (one launch)
    split_all<<<768, 256>>>(W2, W3, W4);

    // G1 + enc1: s1 spikes directly from x @ W1^T + b1
    g1_enc1<<<dim3(8, 16), 256>>>(x, W1, b1, s1);

    // G2: cur2 = s1 @ W2^T + b2  [8192,128], K=256  (3-split)
    mma_gemm_split<3,false><<<dim3(1, 64), 256, SMEM3>>>(
        s1, w2h, w2m, w2l, b2, cur2, nullptr, 8192, 128, 256);
    enc2_scan<<<512, 256>>>();

    // G3 + dec1: s3 spikes directly from spk @ W3^T + b3  [8192,256], K=128
    mma_gemm_split<3,true><<<dim3(2, 64), 256, SMEM3>>>(
        spk, w3h, w3m, w3l, b3, nullptr, s3, 8192, 256, 128);

    // G4 fused with m4 scan + output writes
    gemm4_fused<<<dim3(8, 64), 256, F_SMEM>>>(s3, w4h, w4l, b4, (float*)d_out);
}

// round 8
// speedup vs baseline: 7.2276x; 1.0682x over previous
#include <cuda_runtime.h>
#include <cuda_bf16.h>
#include <cstdint>

// ---------------------------------------------------------------------------
// Net_9560597201379 : SNN encoder/decoder.
//   G1+enc1 fused: fp32 scalar-FMA GEMM (exact sequential-k chain).
//   G2: HMMA 3-way-split W -> cur2 ; enc2 scan standalone (cross-k coupling).
//   G3+dec1 fused: HMMA 3-way-split W, m3 scan in registers -> s3 direct.
//   G4 fused: HMMA 2-way split W4 + m4 scan + output stores.
// HMMA fragment loads via ldmatrix.x4 (conflict-free on 144B-padded rows);
// MMA issue order identical to the proven scalar-LDS version -> bitwise-same.
// ---------------------------------------------------------------------------

__device__ __nv_bfloat16  g_s1  [8*1024*256];
__device__ float          g_cur2[8*1024*128];
__device__ __nv_bfloat16  g_spk [8*1024*128];
__device__ __nv_bfloat16  g_s3  [8*8192*256];
__device__ __nv_bfloat16  g_w2hi[128*256], g_w2mi[128*256], g_w2lo[128*256];
__device__ __nv_bfloat16  g_w3hi[256*128], g_w3mi[256*128], g_w3lo[256*128];
__device__ __nv_bfloat16  g_w4hi[512*256], g_w4lo[512*256];

// ===================== helpers =============================================

__device__ __forceinline__ uint32_t smem_u32(const void* p) {
    uint32_t a;
    asm("{ .reg .u64 t; cvta.to.shared.u64 t, %1; cvt.u32.u64 %0, t; }"
        : "=r"(a) : "l"(p));
    return a;
}

__device__ __forceinline__ void cp16(uint32_t s, const void* g) {
    asm volatile("cp.async.cg.shared.global [%0], [%1], 16;" :: "r"(s), "l"(g));
}
__device__ __forceinline__ void cp_commit() {
    asm volatile("cp.async.commit_group;");
}
template <int N> __device__ __forceinline__ void cp_wait() {
    asm volatile("cp.async.wait_group %0;" :: "n"(N));
}

__device__ __forceinline__ void mma16816(float* d, const uint32_t* a,
                                         uint32_t b0, uint32_t b1) {
    asm volatile(
        "mma.sync.aligned.m16n8k16.row.col.f32.bf16.bf16.f32 "
        "{%0,%1,%2,%3}, {%4,%5,%6,%7}, {%8,%9}, {%0,%1,%2,%3};"
        : "+f"(d[0]), "+f"(d[1]), "+f"(d[2]), "+f"(d[3])
        : "r"(a[0]), "r"(a[1]), "r"(a[2]), "r"(a[3]), "r"(b0), "r"(b1));
}

__device__ __forceinline__ void ldsm4(uint32_t* r, uint32_t a) {
    asm volatile("ldmatrix.sync.aligned.m8n8.x4.shared.b16 {%0,%1,%2,%3}, [%4];"
                 : "=r"(r[0]), "=r"(r[1]), "=r"(r[2]), "=r"(r[3]) : "r"(a));
}

// spike pair -> packed bf16x2 bits (1.0f = 0x3F80, 0.0f = 0x0000)
__device__ __forceinline__ uint32_t spike_pack(float m0, float m1, float th) {
    uint32_t lo = (m0 - th > 0.0f) ? 0x3F80u : 0u;
    uint32_t hi = (m1 - th > 0.0f) ? 0x3F80u : 0u;
    return lo | (hi << 16);
}

static const int ROWB = 144;              // bytes per smem row (72 bf16, padded)
static const int MATB = 128 * ROWB;       // 18432 B per 128x64 matrix tile

// ===================== G1 + enc1 fused =====================================
// grid = (8,16), block 256.  Exact chain: fma.rn ascending k, +bias last.

__global__ __launch_bounds__(256) void g1_enc1(
    const float* __restrict__ A, const float* __restrict__ B,
    const float* __restrict__ bias, __nv_bfloat16* __restrict__ S1)
{
    __shared__ float As[16][68];   // [k][row]
    __shared__ float Bs[16][36];   // [k][col]

    const int tid = threadIdx.x;
    const int bx = blockIdx.x, by = blockIdx.y;
    const int arow = tid >> 2, akq = (tid & 3) * 4;
    const int brow = tid >> 3, bkq = (tid & 7) * 2;
    const int tr = (tid >> 4) * 4, tc = (tid & 15) * 2;

    const float* Ab = A + (size_t)(by * 64) * 512;
    const float* Bb = B + (size_t)(bx * 32) * 512;

    float4 ar = *reinterpret_cast<const float4*>(Ab + arow * 512 + akq);
    float2 br = *reinterpret_cast<const float2*>(Bb + brow * 512 + bkq);

    float acc[4][2];
#pragma unroll
    for (int i = 0; i < 4; i++) { acc[i][0] = 0.0f; acc[i][1] = 0.0f; }

    for (int c = 0; c < 32; c++) {
        As[akq + 0][arow] = ar.x;
        As[akq + 1][arow] = ar.y;
        As[akq + 2][arow] = ar.z;
        As[akq + 3][arow] = ar.w;
        Bs[bkq + 0][brow] = br.x;
        Bs[bkq + 1][brow] = br.y;
        __syncthreads();
        if (c + 1 < 32) {
            ar = *reinterpret_cast<const float4*>(Ab + arow * 512 + (c + 1) * 16 + akq);
            br = *reinterpret_cast<const float2*>(Bb + brow * 512 + (c + 1) * 16 + bkq);
        }
#pragma unroll
        for (int kk = 0; kk < 16; kk++) {
            float4 av = *reinterpret_cast<const float4*>(&As[kk][tr]);
            float b0 = Bs[kk][tc], b1 = Bs[kk][tc + 1];
            acc[0][0] = fmaf(av.x, b0, acc[0][0]);
            acc[0][1] = fmaf(av.x, b1, acc[0][1]);
            acc[1][0] = fmaf(av.y, b0, acc[1][0]);
            acc[1][1] = fmaf(av.y, b1, acc[1][1]);
            acc[2][0] = fmaf(av.z, b0, acc[2][0]);
            acc[2][1] = fmaf(av.z, b1, acc[2][1]);
            acc[3][0] = fmaf(av.w, b0, acc[3][0]);
            acc[3][1] = fmaf(av.w, b1, acc[3][1]);
        }
        __syncthreads();
    }

    const int col = bx * 32 + tc;
    const float bv0 = bias[col], bv1 = bias[col + 1];
#pragma unroll
    for (int i = 0; i < 4; i++) {
        const int row = by * 64 + tr + i;
        float c0 = acc[i][0] + bv0;
        float c1 = acc[i][1] + bv1;
        float m0 = 0.0f, m1 = 0.0f;
        uint32_t* dst = reinterpret_cast<uint32_t*>(S1 + (size_t)row * 256 + col);
#pragma unroll
        for (int k = 0; k < 8; k++) {
            float r0 = (m0 - 1.0f > 0.0f) ? 1.0f : 0.0f;
            float r1 = (m1 - 1.0f > 0.0f) ? 1.0f : 0.0f;
            m0 = 0.9f * m0 + c0 - r0;
            m1 = 0.9f * m1 + c1 - r1;
            dst[k * 131072] = spike_pack(m0, m1, 1.0f);
        }
    }
}

// ===================== generic HMMA GEMM (G2 / G3+dec1) ====================
// ldmatrix fragment loads; MMA issue order identical to scalar-LDS version.

template <int NB, bool DEC1>
__global__ __launch_bounds__(256, 2) void mma_gemm_split(
    const __nv_bfloat16* __restrict__ A,
    const __nv_bfloat16* __restrict__ B0,
    const __nv_bfloat16* __restrict__ B1,
    const __nv_bfloat16* __restrict__ B2,
    const float* __restrict__ bias,
    float* __restrict__ C, __nv_bfloat16* __restrict__ S3,
    int M, int N, int K)
{
    constexpr int STAGEB = (1 + NB) * MATB;
    extern __shared__ char sm[];
    const uint32_t sb = smem_u32(sm);
    const int tid = threadIdx.x, wid = tid >> 5, lane = tid & 31;
    const int bx = blockIdx.x, by = blockIdx.y;
    const int g = lane >> 2, tig = lane & 3;
    const int wm = (wid >> 2) * 64, wn = (wid & 3) * 32;

    const __nv_bfloat16* Ab = A + (size_t)(by * 128) * K;
    const __nv_bfloat16* Bb[NB];
    Bb[0] = B0 + (size_t)(bx * 128) * K;
    if (NB > 1) Bb[1] = B1 + (size_t)(bx * 128) * K;
    if (NB > 2) Bb[2] = B2 + (size_t)(bx * 128) * K;

    const int lrow = tid >> 3;
    const int lcg  = (tid & 7) * 8;

    // ldmatrix per-thread offsets
    const uint32_t aoff = (uint32_t)((wm + (lane & 7) + ((lane >> 3) & 1) * 8) * ROWB
                                     + (lane >> 4) * 16);
    const uint32_t boff = (uint32_t)((wn + (lane & 7) + (lane >> 4) * 8) * ROWB
                                     + ((lane >> 3) & 1) * 16);

    float acc[4][4][4];
#pragma unroll
    for (int i = 0; i < 4; i++)
#pragma unroll
        for (int j = 0; j < 4; j++)
#pragma unroll
            for (int q = 0; q < 4; q++) acc[i][j][q] = 0.0f;

    const int nchunk = K >> 6;

    auto load_stage = [&](int c, int s) {
        const int k0 = c * 64;
        uint32_t base = sb + s * STAGEB;
#pragma unroll
        for (int i = 0; i < 4; i++) {
            int row = lrow + i * 32;
            uint32_t so = base + row * ROWB + lcg * 2;
            cp16(so, Ab + (size_t)row * K + k0 + lcg);
#pragma unroll
            for (int b = 0; b < NB; b++)
                cp16(so + (b + 1) * MATB, Bb[b] + (size_t)row * K + k0 + lcg);
        }
        cp_commit();
    };

    load_stage(0, 0);

    for (int c = 0; c < nchunk; c++) {
        if (c + 1 < nchunk) { load_stage(c + 1, (c + 1) & 1); cp_wait<1>(); }
        else                { cp_wait<0>(); }
        __syncthreads();

        const uint32_t abase = sb + (c & 1) * STAGEB + aoff;
        const uint32_t bbase = sb + (c & 1) * STAGEB + boff;

#pragma unroll
        for (int kk = 0; kk < 4; kk++) {
            uint32_t a[4][4];
#pragma unroll
            for (int mt = 0; mt < 4; mt++)
                ldsm4(a[mt], abase + mt * 16 * ROWB + kk * 32);
            uint32_t bf[NB][2][4];       // [split][ntpair][b0,b1,b0',b1']
#pragma unroll
            for (int b = 0; b < NB; b++)
#pragma unroll
                for (int np = 0; np < 2; np++)
                    ldsm4(bf[b][np], bbase + (b + 1) * MATB + np * 16 * ROWB + kk * 32);
#pragma unroll
            for (int nt = 0; nt < 4; nt++) {
#pragma unroll
                for (int b = 0; b < NB; b++) {
                    uint32_t b0 = bf[b][nt >> 1][(nt & 1) * 2];
                    uint32_t b1 = bf[b][nt >> 1][(nt & 1) * 2 + 1];
#pragma unroll
                    for (int mt = 0; mt < 4; mt++)
                        mma16816(acc[mt][nt], a[mt], b0, b1);
                }
            }
        }
        __syncthreads();
    }

#pragma unroll
    for (int mt = 0; mt < 4; mt++) {
#pragma unroll
        for (int nt = 0; nt < 4; nt++) {
            int row = by * 128 + wm + mt * 16 + g;
            int col = bx * 128 + wn + nt * 8 + tig * 2;
            float bv0 = bias[col], bv1 = bias[col + 1];
            if (DEC1) {
#pragma unroll
                for (int h = 0; h < 2; h++) {
                    float c0 = acc[mt][nt][2*h]   + bv0;
                    float c1 = acc[mt][nt][2*h+1] + bv1;
                    float m0 = 0.0f, m1 = 0.0f;
                    uint32_t* dst = reinterpret_cast<uint32_t*>(
                        S3 + (size_t)(row + h * 8) * 256 + col);
#pragma unroll
                    for (int j = 0; j < 8; j++) {
                        float r0 = (m0 - 1.0f > 0.0f) ? 1.0f : 0.0f;
                        float r1 = (m1 - 1.0f > 0.0f) ? 1.0f : 0.0f;
                        m0 = 0.9f * m0 + c0 - r0;
                        m1 = 0.9f * m1 + c1 - r1;
                        dst[j * 1048576] = spike_pack(m0, m1, 1.0f);
                    }
                }
            } else {
                float2 v0 = make_float2(acc[mt][nt][0] + bv0, acc[mt][nt][1] + bv1);
                float2 v1 = make_float2(acc[mt][nt][2] + bv0, acc[mt][nt][3] + bv1);
                *reinterpret_cast<float2*>(C + (size_t)row * N + col)       = v0;
                *reinterpret_cast<float2*>(C + (size_t)(row + 8) * N + col) = v1;
            }
        }
    }
}

// ===================== fused G4 + m4 scan + output =========================
// grid = (8, 64), block 256 (8 warps 4x2, warp 32x32).  B resident in smem.

static const int F_SBB  = 9216;               // 64 rows * 144 B per B chunk tile
static const int F_SBA  = 8 * F_SBB;          // 73728: B = 2 mats x 4 chunks
static const int F_SMEM = F_SBA + 2 * MATB;   // + A double stage = 110592

__global__ __launch_bounds__(256, 2) void gemm4_fused(
    const __nv_bfloat16* __restrict__ A,      // s3 [65536, 256]
    const __nv_bfloat16* __restrict__ B0,     // w4hi [512, 256]
    const __nv_bfloat16* __restrict__ B1,     // w4lo
    const float* __restrict__ bias,
    float* __restrict__ out)                  // mem @0, spk @ +33554432
{
    extern __shared__ char sm[];
    const uint32_t sb = smem_u32(sm);
    const int tid = threadIdx.x, wid = tid >> 5, lane = tid & 31;
    const int bx = blockIdx.x, by = blockIdx.y;
    const int g = lane >> 2, tig = lane & 3;
    const int wm = (wid >> 1) * 32, wn = (wid & 1) * 32;

    {
        const __nv_bfloat16* Bsrc[2] = { B0 + (size_t)(bx * 64) * 256,
                                         B1 + (size_t)(bx * 64) * 256 };
#pragma unroll
        for (int b = 0; b < 2; b++)
#pragma unroll
            for (int i = 0; i < 8; i++) {
                int w = tid + i * 256;
                int row = w >> 5, kcg = (w & 31) * 8;
                uint32_t dst = sb + (uint32_t)((b * 4 + (kcg >> 6)) * F_SBB +
                                               row * ROWB + (kcg & 63) * 2);
                cp16(dst, Bsrc[b] + (size_t)row * 256 + kcg);
            }
    }

    const int lrow = tid >> 3;
    const int lcg  = (tid & 7) * 8;
    auto load_stageA = [&](int gc) {
        int j = gc >> 2, kc = gc & 3;
        const __nv_bfloat16* Ab = A + (size_t)(j * 8192 + by * 128) * 256 + kc * 64;
        uint32_t base = sb + (uint32_t)(F_SBA + (gc & 1) * MATB);
#pragma unroll
        for (int i = 0; i < 4; i++) {
            int row = lrow + i * 32;
            cp16(base + row * ROWB + lcg * 2, Ab + (size_t)row * 256 + lcg);
        }
        cp_commit();
    };

    load_stageA(0);

    // ldmatrix per-thread offsets
    const uint32_t aoff = (uint32_t)((wm + (lane & 7) + ((lane >> 3) & 1) * 8) * ROWB
                                     + (lane >> 4) * 16);
    const uint32_t boff = (uint32_t)((wn + (lane & 7) + (lane >> 4) * 8) * ROWB
                                     + ((lane >> 3) & 1) * 16);

    float bv[4][2];
#pragma unroll
    for (int nt = 0; nt < 4; nt++) {
        int col = bx * 64 + wn + nt * 8 + tig * 2;
        bv[nt][0] = bias[col]; bv[nt][1] = bias[col + 1];
    }

    float acc[2][4][4], m4[2][4][4];
#pragma unroll
    for (int i = 0; i < 2; i++)
#pragma unroll
        for (int j = 0; j < 4; j++)
#pragma unroll
            for (int q = 0; q < 4; q++) { acc[i][j][q] = 0.0f; m4[i][j][q] = 0.0f; }

    for (int gc = 0; gc < 32; gc++) {
        if (gc + 1 < 32) { load_stageA(gc + 1); cp_wait<1>(); }
        else             { cp_wait<0>(); }
        __syncthreads();

        const uint32_t abase = sb + F_SBA + (gc & 1) * MATB + aoff;
        const int kc = gc & 3;

#pragma unroll
        for (int kk = 0; kk < 4; kk++) {
            uint32_t a[2][4];
#pragma unroll
            for (int mt = 0; mt < 2; mt++)
                ldsm4(a[mt], abase + mt * 16 * ROWB + kk * 32);
            uint32_t bf[2][2][4];
#pragma unroll
            for (int b = 0; b < 2; b++)
#pragma unroll
                for (int np = 0; np < 2; np++)
                    ldsm4(bf[b][np], sb + (b * 4 + kc) * F_SBB + boff
                                        + np * 16 * ROWB + kk * 32);
#pragma unroll
            for (int nt = 0; nt < 4; nt++) {
#pragma unroll
                for (int b = 0; b < 2; b++) {
                    uint32_t b0 = bf[b][nt >> 1][(nt & 1) * 2];
                    uint32_t b1 = bf[b][nt >> 1][(nt & 1) * 2 + 1];
#pragma unroll
                    for (int mt = 0; mt < 2; mt++)
                        mma16816(acc[mt][nt], a[mt], b0, b1);
                }
            }
        }
        __syncthreads();

        if ((gc & 3) == 3) {
            const int j = gc >> 2;
#pragma unroll
            for (int mt = 0; mt < 2; mt++) {
#pragma unroll
                for (int nt = 0; nt < 4; nt++) {
                    int r0  = by * 128 + wm + mt * 16 + g;
                    int col = bx * 64 + wn + nt * 8 + tig * 2;
#pragma unroll
                    for (int h = 0; h < 2; h++) {
                        float c0 = acc[mt][nt][2*h]   + bv[nt][0];
                        float c1 = acc[mt][nt][2*h+1] + bv[nt][1];
                        float m0 = m4[mt][nt][2*h], m1 = m4[mt][nt][2*h+1];
                        float rst0 = (m0 - 20000.0f > 0.0f) ? 20000.0f : 0.0f;
                        float rst1 = (m1 - 20000.0f > 0.0f) ? 20000.0f : 0.0f;
                        m0 = 0.9f * m0 + c0 - rst0;
                        m1 = 0.9f * m1 + c1 - rst1;
                        m4[mt][nt][2*h] = m0; m4[mt][nt][2*h+1] = m1;
                        size_t base = ((size_t)(j * 8192 + r0 + h * 8)) * 512 + col;
                        *reinterpret_cast<float2*>(out + base) = make_float2(m0, m1);
                        float s0 = (m0 - 20000.0f > 0.0f) ? 1.0f : 0.0f;
                        float s1 = (m1 - 20000.0f > 0.0f) ? 1.0f : 0.0f;
                        *reinterpret_cast<float2*>(out + 33554432 + base) =
                            make_float2(s0, s1);
                        acc[mt][nt][2*h] = 0.0f; acc[mt][nt][2*h+1] = 0.0f;
                    }
                }
            }
        }
    }
}

// ===================== split + scan kernels ================================

__global__ void split_all(const float* __restrict__ W2, const float* __restrict__ W3,
                          const float* __restrict__ W4) {
    int b = blockIdx.x;
    if (b < 128) {
        int i = b * 256 + threadIdx.x;
        float w = W2[i];
        __nv_bfloat16 h = __float2bfloat16(w);
        float r1 = w - __bfloat162float(h);
        __nv_bfloat16 m = __float2bfloat16(r1);
        g_w2hi[i] = h; g_w2mi[i] = m;
        g_w2lo[i] = __float2bfloat16(r1 - __bfloat162float(m));
    } else if (b < 256) {
        int i = (b - 128) * 256 + threadIdx.x;
        float w = W3[i];
        __nv_bfloat16 h = __float2bfloat16(w);
        float r1 = w - __bfloat162float(h);
        __nv_bfloat16 m = __float2bfloat16(r1);
        g_w3hi[i] = h; g_w3mi[i] = m;
        g_w3lo[i] = __float2bfloat16(r1 - __bfloat162float(m));
    } else {
        int i = (b - 256) * 256 + threadIdx.x;
        float w = W4[i];
        __nv_bfloat16 h = __float2bfloat16(w);
        g_w4hi[i] = h;
        g_w4lo[i] = __float2bfloat16(w - __bfloat162float(h));
    }
}

__global__ void enc2_scan() {
    int t4 = (blockIdx.x * blockDim.x + threadIdx.x) * 4;   // < 131072
    float m0 = 0.0f, m1 = 0.0f, m2 = 0.0f, m3 = 0.0f;
#pragma unroll
    for (int k = 0; k < 8; k++) {
        float4 c = *reinterpret_cast<const float4*>(&g_cur2[k*131072 + t4]);
        float r0 = (m0 - 1.0f > 0.0f) ? 1.0f : 0.0f;
        float r1 = (m1 - 1.0f > 0.0f) ? 1.0f : 0.0f;
        float r2 = (m2 - 1.0f > 0.0f) ? 1.0f : 0.0f;
        float r3 = (m3 - 1.0f > 0.0f) ? 1.0f : 0.0f;
        m0 = 0.9f * m0 + c.x - r0;
        m1 = 0.9f * m1 + c.y - r1;
        m2 = 0.9f * m2 + c.z - r2;
        m3 = 0.9f * m3 + c.w - r3;
        uint2 sp;
        sp.x = spike_pack(m0, m1, 1.0f);
        sp.y = spike_pack(m2, m3, 1.0f);
        *reinterpret_cast<uint2*>(&g_spk[k*131072 + t4]) = sp;
    }
}

// ===================== launch ==============================================

extern "C" void kernel_launch(void* const* d_in, const int* in_sizes, int n_in,
                              void* d_out, int out_size) {
    const float* x  = (const float*)d_in[0];
    const float* W1 = (const float*)d_in[1];
    const float* b1 = (const float*)d_in[2];
    const float* W2 = (const float*)d_in[3];
    const float* b2 = (const float*)d_in[4];
    const float* W3 = (const float*)d_in[5];
    const float* b3 = (const float*)d_in[6];
    const float* W4 = (const float*)d_in[7];
    const float* b4 = (const float*)d_in[8];

    float *cur2;
    __nv_bfloat16 *s1, *spk, *s3;
    __nv_bfloat16 *w2h, *w2m, *w2l, *w3h, *w3m, *w3l, *w4h, *w4l;
    cudaGetSymbolAddress((void**)&s1,   g_s1);
    cudaGetSymbolAddress((void**)&cur2, g_cur2);
    cudaGetSymbolAddress((void**)&spk,  g_spk);
    cudaGetSymbolAddress((void**)&s3,   g_s3);
    cudaGetSymbolAddress((void**)&w2h,  g_w2hi);
    cudaGetSymbolAddress((void**)&w2m,  g_w2mi);
    cudaGetSymbolAddress((void**)&w2l,  g_w2lo);
    cudaGetSymbolAddress((void**)&w3h,  g_w3hi);
    cudaGetSymbolAddress((void**)&w3m,  g_w3mi);
    cudaGetSymbolAddress((void**)&w3l,  g_w3lo);
    cudaGetSymbolAddress((void**)&w4h,  g_w4hi);
    cudaGetSymbolAddress((void**)&w4l,  g_w4lo);

    const int SMEM3 = 2 * 4 * MATB;   // 147456
    cudaFuncSetAttribute(mma_gemm_split<3,false>,
                         cudaFuncAttributeMaxDynamicSharedMemorySize, SMEM3);
    cudaFuncSetAttribute(mma_gemm_split<3,true>,
                         cudaFuncAttributeMaxDynamicSharedMemorySize, SMEM3);
    cudaFuncSetAttribute(gemm4_fused,
                         cudaFuncAttributeMaxDynamicSharedMemorySize, F_SMEM);

    split_all<<<768, 256>>>(W2, W3, W4);

    // G1 + enc1: s1 spikes directly from x @ W1^T + b1
    g1_enc1<<<dim3(8, 16), 256>>>(x, W1, b1, s1);

    // G2: cur2 = s1 @ W2^T + b2  [8192,128], K=256  (3-split)
    mma_gemm_split<3,false><<<dim3(1, 64), 256, SMEM3>>>(
        s1, w2h, w2m, w2l, b2, cur2, nullptr, 8192, 128, 256);
    enc2_scan<<<128, 256>>>();

    // G3 + dec1: s3 spikes directly from spk @ W3^T + b3  [8192,256], K=128
    mma_gemm_split<3,true><<<dim3(2, 64), 256, SMEM3>>>(
        spk, w3h, w3m, w3l, b3, nullptr, s3, 8192, 256, 128);

    // G4 fused with m4 scan + output writes
    gemm4_fused<<<dim3(8, 64), 256, F_SMEM>>>(s3, w4h, w4l, b4, (float*)d_out);
}